// round 1
// baseline (speedup 1.0000x reference)
#include <cuda_runtime.h>
#include <math.h>

// ---------------- problem constants ----------------
#define Hh 224
#define Ww 224
#define Cc 96
#define WSZ 7
#define NT 49            // tokens per window
#define SHIFT_ 3
#define QS 292           // qkv smem row stride (padded from 288; 292%32=4, 16B-aligned)
#define WPAD 100         // weight tile row stride (conflict-free for lane-stride access)
#define TPB 256
#define SCALE_Q 0.17677669529663687f   // 32^-0.5
#define LN_EPS 1e-5f

#define NTOKENS (8*224*224)            // 401408
#define XELEMS  (NTOKENS*Cc)           // 38535168

// scratch: x after attention residual (input to MLP half)
__device__ float g_x1[XELEMS];

// =====================================================================
// Kernel A: LN1 + shift + window partition + QKV + attention + proj +
//           residual, one block per window.
// smem: xw[49*96] | qkv[49*292] | union( wtile[96*100] , attn[3*49*49] )
// =====================================================================
__global__ __launch_bounds__(TPB) void attn_kernel(
    const float* __restrict__ x,
    const float* __restrict__ mask,
    const float* __restrict__ n1g, const float* __restrict__ n1b,
    const float* __restrict__ qkv_w, const float* __restrict__ qkv_b,
    const float* __restrict__ proj_w, const float* __restrict__ proj_b)
{
    extern __shared__ float sm[];
    float* xw  = sm;                    // 4704 floats
    float* qkv = sm + 4704;             // 14308 floats
    float* un  = sm + 4704 + 14308;     // 9600 floats (union region)

    const int tid  = threadIdx.x;
    const int lane = tid & 31;
    const int wg   = tid >> 5;

    const int blk = blockIdx.x;         // 0..8191
    const int b   = blk >> 10;
    const int wi  = (blk >> 5) & 31;
    const int wj  = blk & 31;

    // ---------------- LN1 + shifted gather into xw ----------------
    {
        const float g0 = n1g[lane], g1 = n1g[lane+32], g2 = n1g[lane+64];
        const float b0 = n1b[lane], b1 = n1b[lane+32], b2 = n1b[lane+64];
        for (int t = wg; t < NT; t += 8) {
            int r  = wi*WSZ + t/WSZ;
            int cl = wj*WSZ + t%WSZ;
            int sr = r + SHIFT_;  if (sr >= Hh) sr -= Hh;
            int sc = cl + SHIFT_; if (sc >= Ww) sc -= Ww;
            const float* xp = x + ((size_t)(b*Hh + sr)*Ww + sc)*Cc;
            float v0 = xp[lane], v1 = xp[lane+32], v2 = xp[lane+64];
            float s = v0 + v1 + v2;
            #pragma unroll
            for (int o = 16; o; o >>= 1) s += __shfl_xor_sync(~0u, s, o);
            float mu = s * (1.0f/96.0f);
            float d0 = v0-mu, d1 = v1-mu, d2 = v2-mu;
            float vs = d0*d0 + d1*d1 + d2*d2;
            #pragma unroll
            for (int o = 16; o; o >>= 1) vs += __shfl_xor_sync(~0u, vs, o);
            float rs = rsqrtf(vs*(1.0f/96.0f) + LN_EPS);
            xw[t*96 + lane]    = d0*rs*g0 + b0;
            xw[t*96 + lane+32] = d1*rs*g1 + b1;
            xw[t*96 + lane+64] = d2*rs*g2 + b2;
        }
    }
    __syncthreads();

    // token slots for this warp-group: t = wg + 8*i, i=0..6 (clamp invalid)
    int ts[7], tc[7];
    #pragma unroll
    for (int i = 0; i < 7; i++) { ts[i] = wg + 8*i; tc[i] = (ts[i] < NT) ? ts[i] : 0; }

    // ---------------- QKV GEMM: 3 chunks of 96 output rows ----------------
    for (int ch = 0; ch < 3; ch++) {
        const float* wsrc = qkv_w + ch*96*96;
        for (int i = tid; i < 96*24; i += TPB) {
            int r = i/24, c4 = (i%24)*4;
            *(float4*)(un + r*WPAD + c4) = *(const float4*)(wsrc + r*96 + c4);
        }
        __syncthreads();

        float acc[7][3];
        #pragma unroll
        for (int i = 0; i < 7; i++) { acc[i][0]=0.f; acc[i][1]=0.f; acc[i][2]=0.f; }
        const float* w0 = un + lane*WPAD;
        #pragma unroll 8
        for (int c = 0; c < 96; c += 4) {
            float4 wa = *(const float4*)(w0 + c);
            float4 wb = *(const float4*)(w0 + 32*WPAD + c);
            float4 wc = *(const float4*)(w0 + 64*WPAD + c);
            #pragma unroll
            for (int i = 0; i < 7; i++) {
                float4 xv = *(const float4*)(xw + tc[i]*96 + c);
                acc[i][0] += xv.x*wa.x + xv.y*wa.y + xv.z*wa.z + xv.w*wa.w;
                acc[i][1] += xv.x*wb.x + xv.y*wb.y + xv.z*wb.z + xv.w*wb.w;
                acc[i][2] += xv.x*wc.x + xv.y*wc.y + xv.z*wc.z + xv.w*wc.w;
            }
        }
        #pragma unroll
        for (int i = 0; i < 7; i++) {
            if (ts[i] < NT) {
                #pragma unroll
                for (int m = 0; m < 3; m++) {
                    int j = ch*96 + lane + 32*m;
                    float v = acc[i][m] + __ldg(qkv_b + j);
                    if (ch == 0) v *= SCALE_Q;     // pre-scale q
                    qkv[ts[i]*QS + j] = v;
                }
            }
        }
        __syncthreads();
    }

    // ---------------- attention scores: s[h][t][u] ----------------
    for (int idx = tid; idx < 3*NT*NT; idx += TPB) {
        int h2  = idx / (NT*NT);
        int rem = idx - h2*(NT*NT);
        int r   = rem / NT;
        int u   = rem - r*NT;
        const float* qp = qkv + r*QS + h2*32;
        const float* kp = qkv + u*QS + 96 + h2*32;
        float s = 0.f;
        #pragma unroll
        for (int d = 0; d < 32; d += 4) {
            float4 q4 = *(const float4*)(qp + d);
            float4 k4 = *(const float4*)(kp + d);
            s += q4.x*k4.x + q4.y*k4.y + q4.z*k4.z + q4.w*k4.w;
        }
        un[idx] = s + __ldg(mask + (size_t)blk*(NT*NT) + rem);
    }
    __syncthreads();

    // ---------------- softmax over 147 rows of 49 ----------------
    for (int row = wg; row < 3*NT; row += 8) {
        float* p = un + row*NT;
        float a0 = p[lane];
        float a1 = (lane < 17) ? p[lane+32] : -1e30f;
        float m = fmaxf(a0, a1);
        #pragma unroll
        for (int o = 16; o; o >>= 1) m = fmaxf(m, __shfl_xor_sync(~0u, m, o));
        float e0 = __expf(a0 - m);
        float e1 = (lane < 17) ? __expf(a1 - m) : 0.f;
        float s = e0 + e1;
        #pragma unroll
        for (int o = 16; o; o >>= 1) s += __shfl_xor_sync(~0u, s, o);
        float inv = 1.0f / s;
        p[lane] = e0 * inv;
        if (lane < 17) p[lane+32] = e1 * inv;
    }
    __syncthreads();

    // ---------------- o = attn @ v  (written over xw) ----------------
    {
        float oacc[7][3];
        #pragma unroll
        for (int i = 0; i < 7; i++) { oacc[i][0]=0.f; oacc[i][1]=0.f; oacc[i][2]=0.f; }
        for (int u = 0; u < NT; u++) {
            float v0 = qkv[u*QS + 192 + lane];
            float v1 = qkv[u*QS + 224 + lane];
            float v2 = qkv[u*QS + 256 + lane];
            #pragma unroll
            for (int i = 0; i < 7; i++) {
                int t = tc[i];
                oacc[i][0] += un[          t*NT + u] * v0;
                oacc[i][1] += un[  NT*NT + t*NT + u] * v1;
                oacc[i][2] += un[2*NT*NT + t*NT + u] * v2;
            }
        }
        #pragma unroll
        for (int i = 0; i < 7; i++) {
            if (ts[i] < NT) {
                xw[ts[i]*96 + lane]    = oacc[i][0];
                xw[ts[i]*96 + lane+32] = oacc[i][1];
                xw[ts[i]*96 + lane+64] = oacc[i][2];
            }
        }
    }
    __syncthreads();

    // ---------------- proj + residual, scatter back ----------------
    for (int i = tid; i < 96*24; i += TPB) {
        int r = i/24, c4 = (i%24)*4;
        *(float4*)(un + r*WPAD + c4) = *(const float4*)(proj_w + r*96 + c4);
    }
    __syncthreads();
    {
        float acc[7][3];
        #pragma unroll
        for (int i = 0; i < 7; i++) { acc[i][0]=0.f; acc[i][1]=0.f; acc[i][2]=0.f; }
        const float* w0 = un + lane*WPAD;
        #pragma unroll 8
        for (int c = 0; c < 96; c += 4) {
            float4 wa = *(const float4*)(w0 + c);
            float4 wb = *(const float4*)(w0 + 32*WPAD + c);
            float4 wc = *(const float4*)(w0 + 64*WPAD + c);
            #pragma unroll
            for (int i = 0; i < 7; i++) {
                float4 xv = *(const float4*)(xw + tc[i]*96 + c);
                acc[i][0] += xv.x*wa.x + xv.y*wa.y + xv.z*wa.z + xv.w*wa.w;
                acc[i][1] += xv.x*wb.x + xv.y*wb.y + xv.z*wb.z + xv.w*wb.w;
                acc[i][2] += xv.x*wc.x + xv.y*wc.y + xv.z*wc.z + xv.w*wc.w;
            }
        }
        const float pb0 = __ldg(proj_b + lane);
        const float pb1 = __ldg(proj_b + lane + 32);
        const float pb2 = __ldg(proj_b + lane + 64);
        #pragma unroll
        for (int i = 0; i < 7; i++) {
            int t = ts[i];
            if (t < NT) {
                int r  = wi*WSZ + t/WSZ;
                int cl = wj*WSZ + t%WSZ;
                int sr = r + SHIFT_;  if (sr >= Hh) sr -= Hh;
                int sc = cl + SHIFT_; if (sc >= Ww) sc -= Ww;
                size_t g = ((size_t)(b*Hh + sr)*Ww + sc)*Cc;
                g_x1[g + lane]    = x[g + lane]    + acc[i][0] + pb0;
                g_x1[g + lane+32] = x[g + lane+32] + acc[i][1] + pb1;
                g_x1[g + lane+64] = x[g + lane+64] + acc[i][2] + pb2;
            }
        }
    }
}

// =====================================================================
// Kernel B: LN2 + fc1 + exact GELU + fc2 + residual, 32 tokens / block
// smem: xn[32*96] | h[32*384] | wtile[128*100]
// =====================================================================
__global__ __launch_bounds__(TPB) void mlp_kernel(
    const float* __restrict__ n2g, const float* __restrict__ n2b,
    const float* __restrict__ fc1_w, const float* __restrict__ fc1_b,
    const float* __restrict__ fc2_w, const float* __restrict__ fc2_b,
    float* __restrict__ out)
{
    extern __shared__ float sm[];
    float* xn = sm;                 // 3072
    float* hb = sm + 3072;          // 12288
    float* wt = sm + 3072 + 12288;  // 12800

    const int tid  = threadIdx.x;
    const int lane = tid & 31;
    const int wg   = tid >> 5;
    const size_t tok0 = (size_t)blockIdx.x * 32;

    // ---------------- LN2 ----------------
    {
        const float g0 = n2g[lane], g1 = n2g[lane+32], g2 = n2g[lane+64];
        const float b0 = n2b[lane], b1 = n2b[lane+32], b2 = n2b[lane+64];
        for (int t = wg; t < 32; t += 8) {
            const float* xp = g_x1 + (tok0 + t)*Cc;
            float v0 = xp[lane], v1 = xp[lane+32], v2 = xp[lane+64];
            float s = v0 + v1 + v2;
            #pragma unroll
            for (int o = 16; o; o >>= 1) s += __shfl_xor_sync(~0u, s, o);
            float mu = s * (1.0f/96.0f);
            float d0 = v0-mu, d1 = v1-mu, d2 = v2-mu;
            float vs = d0*d0 + d1*d1 + d2*d2;
            #pragma unroll
            for (int o = 16; o; o >>= 1) vs += __shfl_xor_sync(~0u, vs, o);
            float rs = rsqrtf(vs*(1.0f/96.0f) + LN_EPS);
            xn[t*96 + lane]    = d0*rs*g0 + b0;
            xn[t*96 + lane+32] = d1*rs*g1 + b1;
            xn[t*96 + lane+64] = d2*rs*g2 + b2;
        }
    }
    __syncthreads();

    const int t0 = wg*4;   // 4 consecutive tokens per warp-group

    // ---------------- fc1 + GELU: 3 chunks of 128 j-rows ----------------
    for (int ch = 0; ch < 3; ch++) {
        const float* wsrc = fc1_w + ch*128*96;
        for (int i = tid; i < 128*24; i += TPB) {
            int r = i/24, c4 = (i%24)*4;
            *(float4*)(wt + r*WPAD + c4) = *(const float4*)(wsrc + r*96 + c4);
        }
        __syncthreads();

        float acc[4][4];
        #pragma unroll
        for (int i = 0; i < 4; i++)
            #pragma unroll
            for (int m = 0; m < 4; m++) acc[i][m] = 0.f;

        const float* w0 = wt + lane*WPAD;
        #pragma unroll 6
        for (int c = 0; c < 96; c += 4) {
            float4 wv0 = *(const float4*)(w0 + c);
            float4 wv1 = *(const float4*)(w0 + 32*WPAD + c);
            float4 wv2 = *(const float4*)(w0 + 64*WPAD + c);
            float4 wv3 = *(const float4*)(w0 + 96*WPAD + c);
            #pragma unroll
            for (int i = 0; i < 4; i++) {
                float4 xv = *(const float4*)(xn + (t0+i)*96 + c);
                acc[i][0] += xv.x*wv0.x + xv.y*wv0.y + xv.z*wv0.z + xv.w*wv0.w;
                acc[i][1] += xv.x*wv1.x + xv.y*wv1.y + xv.z*wv1.z + xv.w*wv1.w;
                acc[i][2] += xv.x*wv2.x + xv.y*wv2.y + xv.z*wv2.z + xv.w*wv2.w;
                acc[i][3] += xv.x*wv3.x + xv.y*wv3.y + xv.z*wv3.z + xv.w*wv3.w;
            }
        }
        #pragma unroll
        for (int i = 0; i < 4; i++)
            #pragma unroll
            for (int m = 0; m < 4; m++) {
                int j = ch*128 + lane + 32*m;
                float v = acc[i][m] + __ldg(fc1_b + j);
                v = 0.5f * v * (1.0f + erff(v * 0.70710678118654752f));  // exact GELU
                hb[(t0+i)*384 + j] = v;
            }
        __syncthreads();
    }

    // ---------------- fc2: 4 K-chunks of 96 ----------------
    float acc2[4][3];
    #pragma unroll
    for (int i = 0; i < 4; i++) { acc2[i][0]=0.f; acc2[i][1]=0.f; acc2[i][2]=0.f; }

    for (int kc = 0; kc < 4; kc++) {
        for (int i = tid; i < 96*24; i += TPB) {
            int r = i/24, c4 = (i%24)*4;
            *(float4*)(wt + r*WPAD + c4) = *(const float4*)(fc2_w + r*384 + kc*96 + c4);
        }
        __syncthreads();

        const float* w0 = wt + lane*WPAD;
        #pragma unroll 6
        for (int c = 0; c < 96; c += 4) {
            float4 wv0 = *(const float4*)(w0 + c);
            float4 wv1 = *(const float4*)(w0 + 32*WPAD + c);
            float4 wv2 = *(const float4*)(w0 + 64*WPAD + c);
            #pragma unroll
            for (int i = 0; i < 4; i++) {
                float4 xv = *(const float4*)(hb + (t0+i)*384 + kc*96 + c);
                acc2[i][0] += xv.x*wv0.x + xv.y*wv0.y + xv.z*wv0.z + xv.w*wv0.w;
                acc2[i][1] += xv.x*wv1.x + xv.y*wv1.y + xv.z*wv1.z + xv.w*wv1.w;
                acc2[i][2] += xv.x*wv2.x + xv.y*wv2.y + xv.z*wv2.z + xv.w*wv2.w;
            }
        }
        __syncthreads();
    }

    // ---------------- residual + store ----------------
    const float fb0 = __ldg(fc2_b + lane);
    const float fb1 = __ldg(fc2_b + lane + 32);
    const float fb2 = __ldg(fc2_b + lane + 64);
    #pragma unroll
    for (int i = 0; i < 4; i++) {
        size_t g = (tok0 + t0 + i)*Cc;
        out[g + lane]    = g_x1[g + lane]    + acc2[i][0] + fb0;
        out[g + lane+32] = g_x1[g + lane+32] + acc2[i][1] + fb1;
        out[g + lane+64] = g_x1[g + lane+64] + acc2[i][2] + fb2;
    }
}

// =====================================================================
extern "C" void kernel_launch(void* const* d_in, const int* in_sizes, int n_in,
                              void* d_out, int out_size)
{
    (void)in_sizes; (void)n_in; (void)out_size;
    const float* x      = (const float*)d_in[0];
    const float* mask   = (const float*)d_in[1];
    const float* n1g    = (const float*)d_in[2];
    const float* n1b    = (const float*)d_in[3];
    const float* qkv_w  = (const float*)d_in[4];
    const float* qkv_b  = (const float*)d_in[5];
    const float* proj_w = (const float*)d_in[6];
    const float* proj_b = (const float*)d_in[7];
    const float* n2g    = (const float*)d_in[8];
    const float* n2b    = (const float*)d_in[9];
    const float* fc1_w  = (const float*)d_in[10];
    const float* fc1_b  = (const float*)d_in[11];
    const float* fc2_w  = (const float*)d_in[12];
    const float* fc2_b  = (const float*)d_in[13];
    float* out = (float*)d_out;

    const int smA = (4704 + 14308 + 9600) * 4;          // 114448 B
    const int smB = (3072 + 12288 + 12800) * 4;         // 112640 B
    cudaFuncSetAttribute(attn_kernel, cudaFuncAttributeMaxDynamicSharedMemorySize, smA);
    cudaFuncSetAttribute(mlp_kernel,  cudaFuncAttributeMaxDynamicSharedMemorySize, smB);

    attn_kernel<<<8192, TPB, smA>>>(x, mask, n1g, n1b, qkv_w, qkv_b, proj_w, proj_b);
    mlp_kernel<<<NTOKENS/32, TPB, smB>>>(n2g, n2b, fc1_w, fc1_b, fc2_w, fc2_b, out);
}

// round 3
// speedup vs baseline: 2.0129x; 2.0129x over previous
#include <cuda_runtime.h>
#include <cuda_bf16.h>
#include <stdint.h>
#include <math.h>

// ---------------- problem constants ----------------
#define Hh 224
#define Ww 224
#define Cc 96
#define NT 49
#define QS 292
#define SCALE_Q 0.17677669529663687f
#define LN_EPS 1e-5f
#define NTOKENS (8*224*224)          // 401408
#define MTILES  (NTOKENS/128)        // 3136

// ---------------- scratch (bf16 activation pipeline) ----------------
__device__ __nv_bfloat16 g_xw [(size_t)NTOKENS*96];    // LN1 out, window order
__device__ __nv_bfloat16 g_qkv[(size_t)NTOKENS*288];   // qkv (q pre-scaled), window order
__device__ __nv_bfloat16 g_o  [(size_t)NTOKENS*96];    // attention out, window order
__device__ float         g_x1 [(size_t)NTOKENS*96];    // x + attn residual (fp32, natural)
__device__ __nv_bfloat16 g_x2 [(size_t)NTOKENS*96];    // LN2 out (natural)
__device__ __nv_bfloat16 g_h  [(size_t)NTOKENS*384];   // fc1+GELU out (natural)

// =====================================================================
// helpers
// =====================================================================
__device__ __forceinline__ uint32_t smem_u32(const void* p) {
    uint32_t a;
    asm("{ .reg .u64 t; cvta.to.shared.u64 t, %1; cvt.u32.u64 %0, t; }" : "=r"(a) : "l"(p));
    return a;
}
__device__ __forceinline__ void ldsm4(uint32_t& r0, uint32_t& r1, uint32_t& r2, uint32_t& r3, uint32_t addr) {
    asm volatile("ldmatrix.sync.aligned.m8n8.x4.shared.b16 {%0,%1,%2,%3}, [%4];"
        : "=r"(r0), "=r"(r1), "=r"(r2), "=r"(r3) : "r"(addr));
}
__device__ __forceinline__ void mma16816(float* c, uint32_t a0, uint32_t a1, uint32_t a2, uint32_t a3,
                                         uint32_t b0, uint32_t b1) {
    asm volatile("mma.sync.aligned.m16n8k16.row.col.f32.bf16.bf16.f32 "
        "{%0,%1,%2,%3},{%4,%5,%6,%7},{%8,%9},{%0,%1,%2,%3};"
        : "+f"(c[0]), "+f"(c[1]), "+f"(c[2]), "+f"(c[3])
        : "r"(a0), "r"(a1), "r"(a2), "r"(a3), "r"(b0), "r"(b1));
}
__device__ __forceinline__ uint4 pack8f(const float* p) {
    float4 a = *(const float4*)p, b = *(const float4*)(p + 4);
    __nv_bfloat162 q0 = __floats2bfloat162_rn(a.x, a.y), q1 = __floats2bfloat162_rn(a.z, a.w);
    __nv_bfloat162 q2 = __floats2bfloat162_rn(b.x, b.y), q3 = __floats2bfloat162_rn(b.z, b.w);
    uint4 r;
    r.x = *(uint32_t*)&q0; r.y = *(uint32_t*)&q1; r.z = *(uint32_t*)&q2; r.w = *(uint32_t*)&q3;
    return r;
}
__device__ __forceinline__ uint32_t packbf2(float a, float b) {
    __nv_bfloat162 p = __floats2bfloat162_rn(a, b);
    return *(uint32_t*)&p;
}

// copy fp32 weights [Nr x K] -> smem bf16, row stride K+8
template <int K>
__device__ __forceinline__ void copy_B(__nv_bfloat16* Bs, const float* w, int Nr) {
    const int C8 = K / 8, S = K + 8;
    for (int i = threadIdx.x; i < Nr * C8; i += blockDim.x) {
        int n = i / C8, c8 = i % C8;
        *(uint4*)(Bs + n * S + c8 * 8) = pack8f(w + n * K + c8 * 8);
    }
}
// copy bf16 activations [128 x K] -> smem, row stride K+8
template <int K>
__device__ __forceinline__ void copy_A(__nv_bfloat16* As, const __nv_bfloat16* a0) {
    const int C8 = K / 8, S = K + 8;
    for (int i = threadIdx.x; i < 128 * C8; i += blockDim.x) {
        int r = i / C8, c8 = i % C8;
        *(uint4*)(As + r * S + c8 * 8) = *(const uint4*)(a0 + (size_t)r * K + c8 * 8);
    }
}

// warp computes 16 rows x 96 cols; c[12][4]
template <int K>
__device__ __forceinline__ void mma_chunk(float c[12][4], uint32_t a_base, uint32_t b_base, int lane, int m0) {
    const int SB = (K + 8) * 2;   // row stride bytes
    uint32_t a_addr = a_base + (uint32_t)(m0 + (lane & 7) + ((lane >> 3) & 1) * 8) * SB + (lane >> 4) * 16;
    uint32_t b_addr = b_base + (uint32_t)((lane & 7) + (lane >> 4) * 8) * SB + ((lane >> 3) & 1) * 16;
    #pragma unroll
    for (int ks = 0; ks < K / 16; ks++) {
        uint32_t a0, a1, a2, a3;
        ldsm4(a0, a1, a2, a3, a_addr + ks * 32);
        #pragma unroll
        for (int j = 0; j < 6; j++) {
            uint32_t b0, b1, b2, b3;
            ldsm4(b0, b1, b2, b3, b_addr + (uint32_t)j * 16 * SB + ks * 32);
            mma16816(c[2 * j],     a0, a1, a2, a3, b0, b1);
            mma16816(c[2 * j + 1], a0, a1, a2, a3, b2, b3);
        }
    }
}

// =====================================================================
// Kernel 1: LN1 + cyclic shift + window gather -> g_xw bf16
// =====================================================================
__global__ __launch_bounds__(256) void ln1_kernel(
    const float* __restrict__ x, const float* __restrict__ g, const float* __restrict__ bb)
{
    const int tid = threadIdx.x, lane = tid & 31, wg = tid >> 5;
    const int blk = blockIdx.x;
    const int b = blk >> 10, wi = (blk >> 5) & 31, wj = blk & 31;
    const float g0 = g[lane], g1 = g[lane + 32], g2 = g[lane + 64];
    const float b0 = bb[lane], b1 = bb[lane + 32], b2 = bb[lane + 64];
    for (int t = wg; t < NT; t += 8) {
        int r  = wi * 7 + t / 7;
        int cl = wj * 7 + t % 7;
        int sr = r + 3;  if (sr >= Hh) sr -= Hh;
        int sc = cl + 3; if (sc >= Ww) sc -= Ww;
        const float* xp = x + ((size_t)(b * Hh + sr) * Ww + sc) * Cc;
        float v0 = xp[lane], v1 = xp[lane + 32], v2 = xp[lane + 64];
        float s = v0 + v1 + v2;
        #pragma unroll
        for (int o = 16; o; o >>= 1) s += __shfl_xor_sync(~0u, s, o);
        float mu = s * (1.0f / 96.0f);
        float d0 = v0 - mu, d1 = v1 - mu, d2 = v2 - mu;
        float vs = d0 * d0 + d1 * d1 + d2 * d2;
        #pragma unroll
        for (int o = 16; o; o >>= 1) vs += __shfl_xor_sync(~0u, vs, o);
        float rs = rsqrtf(vs * (1.0f / 96.0f) + LN_EPS);
        __nv_bfloat16* dst = g_xw + ((size_t)blk * NT + t) * 96;
        dst[lane]      = __float2bfloat16(d0 * rs * g0 + b0);
        dst[lane + 32] = __float2bfloat16(d1 * rs * g1 + b1);
        dst[lane + 64] = __float2bfloat16(d2 * rs * g2 + b2);
    }
}

// =====================================================================
// GEMM qkv: [128x96] @ [288x96]^T -> g_qkv bf16 (+bias, q pre-scale)
// =====================================================================
__global__ __launch_bounds__(256) void gemm_qkv_kernel(
    const float* __restrict__ w, const float* __restrict__ bias)
{
    extern __shared__ __nv_bfloat16 smh[];
    __nv_bfloat16* As = smh;                 // 128*104
    __nv_bfloat16* Bs = smh + 128 * 104;     // 288*104
    const int tid = threadIdx.x, lane = tid & 31, wid = tid >> 5;
    copy_A<96>(As, g_xw + (size_t)blockIdx.x * 128 * 96);
    copy_B<96>(Bs, w, 288);
    __syncthreads();
    const uint32_t a_base = smem_u32(As), b_base = smem_u32(Bs);
    const int m0 = wid * 16;
    const int row0 = blockIdx.x * 128 + m0 + (lane >> 2);
    for (int ch = 0; ch < 3; ch++) {
        float c[12][4];
        #pragma unroll
        for (int j = 0; j < 12; j++) { c[j][0]=0.f; c[j][1]=0.f; c[j][2]=0.f; c[j][3]=0.f; }
        mma_chunk<96>(c, a_base, b_base + (uint32_t)ch * 96 * 208, lane, m0);
        const float qs = (ch == 0) ? SCALE_Q : 1.0f;
        #pragma unroll
        for (int j = 0; j < 12; j++) {
            int col = ch * 96 + j * 8 + (lane & 3) * 2;
            float bi0 = __ldg(bias + col), bi1 = __ldg(bias + col + 1);
            *(uint32_t*)(g_qkv + (size_t)row0 * 288 + col) =
                packbf2((c[j][0] + bi0) * qs, (c[j][1] + bi1) * qs);
            *(uint32_t*)(g_qkv + (size_t)(row0 + 8) * 288 + col) =
                packbf2((c[j][2] + bi0) * qs, (c[j][3] + bi1) * qs);
        }
    }
}

// =====================================================================
// attention core per window: scores + softmax + AV (fp32), bf16 I/O
// =====================================================================
__global__ __launch_bounds__(256) void attn_core_kernel(const float* __restrict__ mask)
{
    extern __shared__ float smf[];
    float* qs = smf;             // 49*292
    float* un = smf + NT * QS;   // 3*49*49 (reused for o staging)
    const int tid = threadIdx.x, lane = tid & 31, wg = tid >> 5;
    const int blk = blockIdx.x;

    for (int i = tid; i < NT * 36; i += 256) {
        int t = i / 36, c8 = i % 36;
        uint4 v = *(const uint4*)(g_qkv + ((size_t)blk * NT + t) * 288 + c8 * 8);
        float2 f0 = __bfloat1622float2(*(__nv_bfloat162*)&v.x);
        float2 f1 = __bfloat1622float2(*(__nv_bfloat162*)&v.y);
        float2 f2 = __bfloat1622float2(*(__nv_bfloat162*)&v.z);
        float2 f3 = __bfloat1622float2(*(__nv_bfloat162*)&v.w);
        float* dst = qs + t * QS + c8 * 8;
        *(float4*)dst       = make_float4(f0.x, f0.y, f1.x, f1.y);
        *(float4*)(dst + 4) = make_float4(f2.x, f2.y, f3.x, f3.y);
    }
    __syncthreads();

    for (int idx = tid; idx < 3 * NT * NT; idx += 256) {
        int h2 = idx / (NT * NT);
        int rem = idx - h2 * (NT * NT);
        int r = rem / NT;
        int u = rem - r * NT;
        const float* qp = qs + r * QS + h2 * 32;
        const float* kp = qs + u * QS + 96 + h2 * 32;
        float s = 0.f;
        #pragma unroll
        for (int d = 0; d < 32; d += 4) {
            float4 q4 = *(const float4*)(qp + d);
            float4 k4 = *(const float4*)(kp + d);
            s += q4.x * k4.x + q4.y * k4.y + q4.z * k4.z + q4.w * k4.w;
        }
        un[idx] = s + __ldg(mask + (size_t)blk * (NT * NT) + rem);
    }
    __syncthreads();

    for (int row = wg; row < 3 * NT; row += 8) {
        float* p = un + row * NT;
        float a0 = p[lane];
        float a1 = (lane < 17) ? p[lane + 32] : -1e30f;
        float m = fmaxf(a0, a1);
        #pragma unroll
        for (int o = 16; o; o >>= 1) m = fmaxf(m, __shfl_xor_sync(~0u, m, o));
        float e0 = __expf(a0 - m);
        float e1 = (lane < 17) ? __expf(a1 - m) : 0.f;
        float s = e0 + e1;
        #pragma unroll
        for (int o = 16; o; o >>= 1) s += __shfl_xor_sync(~0u, s, o);
        float inv = 1.0f / s;
        p[lane] = e0 * inv;
        if (lane < 17) p[lane + 32] = e1 * inv;
    }
    __syncthreads();

    int ts[7], tc[7];
    #pragma unroll
    for (int i = 0; i < 7; i++) { ts[i] = wg + 8 * i; tc[i] = (ts[i] < NT) ? ts[i] : 0; }
    float oacc[7][3];
    #pragma unroll
    for (int i = 0; i < 7; i++) { oacc[i][0] = 0.f; oacc[i][1] = 0.f; oacc[i][2] = 0.f; }
    for (int u = 0; u < NT; u++) {
        float v0 = qs[u * QS + 192 + lane];
        float v1 = qs[u * QS + 224 + lane];
        float v2 = qs[u * QS + 256 + lane];
        #pragma unroll
        for (int i = 0; i < 7; i++) {
            int t = tc[i];
            oacc[i][0] += un[              t * NT + u] * v0;
            oacc[i][1] += un[    NT * NT + t * NT + u] * v1;
            oacc[i][2] += un[2 * NT * NT + t * NT + u] * v2;
        }
    }
    __syncthreads();
    #pragma unroll
    for (int i = 0; i < 7; i++) {
        if (ts[i] < NT) {
            un[ts[i] * 96 + lane]      = oacc[i][0];
            un[ts[i] * 96 + lane + 32] = oacc[i][1];
            un[ts[i] * 96 + lane + 64] = oacc[i][2];
        }
    }
    __syncthreads();
    for (int i = tid; i < NT * 12; i += 256) {
        int t = i / 12, c8 = i % 12;
        *(uint4*)(g_o + ((size_t)blk * NT + t) * 96 + c8 * 8) = pack8f(un + t * 96 + c8 * 8);
    }
}

// =====================================================================
// GEMM proj: + bias + x residual (window-reverse) + fused LN2
// writes g_x1 fp32 and g_x2 bf16 (both natural order)
// =====================================================================
__global__ __launch_bounds__(256) void gemm_proj_kernel(
    const float* __restrict__ w, const float* __restrict__ bias,
    const float* __restrict__ x, const float* __restrict__ n2g, const float* __restrict__ n2b)
{
    extern __shared__ __nv_bfloat16 smh[];
    __nv_bfloat16* As = smh;
    __nv_bfloat16* Bs = smh + 128 * 104;
    const int tid = threadIdx.x, lane = tid & 31, wid = tid >> 5;
    copy_A<96>(As, g_o + (size_t)blockIdx.x * 128 * 96);
    copy_B<96>(Bs, w, 96);
    __syncthreads();
    const uint32_t a_base = smem_u32(As), b_base = smem_u32(Bs);
    const int m0 = wid * 16;

    float c[12][4];
    #pragma unroll
    for (int j = 0; j < 12; j++) { c[j][0]=0.f; c[j][1]=0.f; c[j][2]=0.f; c[j][3]=0.f; }
    mma_chunk<96>(c, a_base, b_base, lane, m0);

    // two rows per thread: m0+lane/4 and +8 (window order) -> natural tokens
    size_t nt_[2];
    #pragma unroll
    for (int h = 0; h < 2; h++) {
        int m = blockIdx.x * 128 + m0 + (lane >> 2) + h * 8;
        int blkw = m / 49, t = m - blkw * 49;
        int b = blkw >> 10, wi = (blkw >> 5) & 31, wj = blkw & 31;
        int r  = wi * 7 + t / 7;
        int cl = wj * 7 + t % 7;
        int sr = r + 3;  if (sr >= Hh) sr -= Hh;
        int sc = cl + 3; if (sc >= Ww) sc -= Ww;
        nt_[h] = ((size_t)(b * Hh + sr)) * Ww + sc;
    }
    float s1[2] = {0.f, 0.f}, s2[2] = {0.f, 0.f};
    #pragma unroll
    for (int j = 0; j < 12; j++) {
        int col = j * 8 + (lane & 3) * 2;
        float bi0 = __ldg(bias + col), bi1 = __ldg(bias + col + 1);
        #pragma unroll
        for (int h = 0; h < 2; h++) {
            float2 xv = *(const float2*)(x + nt_[h] * 96 + col);
            float o0 = c[j][2 * h]     + bi0 + xv.x;
            float o1 = c[j][2 * h + 1] + bi1 + xv.y;
            c[j][2 * h] = o0; c[j][2 * h + 1] = o1;
            *(float2*)(g_x1 + nt_[h] * 96 + col) = make_float2(o0, o1);
            s1[h] += o0 + o1;
            s2[h] += o0 * o0 + o1 * o1;
        }
    }
    #pragma unroll
    for (int h = 0; h < 2; h++) {
        s1[h] += __shfl_xor_sync(~0u, s1[h], 1); s2[h] += __shfl_xor_sync(~0u, s2[h], 1);
        s1[h] += __shfl_xor_sync(~0u, s1[h], 2); s2[h] += __shfl_xor_sync(~0u, s2[h], 2);
    }
    float mu0 = s1[0] * (1.f/96.f), mu1 = s1[1] * (1.f/96.f);
    float rs0 = rsqrtf(s2[0] * (1.f/96.f) - mu0 * mu0 + LN_EPS);
    float rs1 = rsqrtf(s2[1] * (1.f/96.f) - mu1 * mu1 + LN_EPS);
    #pragma unroll
    for (int j = 0; j < 12; j++) {
        int col = j * 8 + (lane & 3) * 2;
        float gg0 = __ldg(n2g + col), gg1 = __ldg(n2g + col + 1);
        float nb0 = __ldg(n2b + col), nb1 = __ldg(n2b + col + 1);
        *(uint32_t*)(g_x2 + nt_[0] * 96 + col) =
            packbf2((c[j][0] - mu0) * rs0 * gg0 + nb0, (c[j][1] - mu0) * rs0 * gg1 + nb1);
        *(uint32_t*)(g_x2 + nt_[1] * 96 + col) =
            packbf2((c[j][2] - mu1) * rs1 * gg0 + nb0, (c[j][3] - mu1) * rs1 * gg1 + nb1);
    }
}

// =====================================================================
// GEMM fc1: [128x96] @ [384x96]^T + bias + exact GELU -> g_h bf16
// =====================================================================
__global__ __launch_bounds__(256) void gemm_fc1_kernel(
    const float* __restrict__ w, const float* __restrict__ bias)
{
    extern __shared__ __nv_bfloat16 smh[];
    __nv_bfloat16* As = smh;
    __nv_bfloat16* Bs = smh + 128 * 104;     // 384*104
    const int tid = threadIdx.x, lane = tid & 31, wid = tid >> 5;
    copy_A<96>(As, g_x2 + (size_t)blockIdx.x * 128 * 96);
    copy_B<96>(Bs, w, 384);
    __syncthreads();
    const uint32_t a_base = smem_u32(As), b_base = smem_u32(Bs);
    const int m0 = wid * 16;
    const size_t row0 = (size_t)blockIdx.x * 128 + m0 + (lane >> 2);
    for (int ch = 0; ch < 4; ch++) {
        float c[12][4];
        #pragma unroll
        for (int j = 0; j < 12; j++) { c[j][0]=0.f; c[j][1]=0.f; c[j][2]=0.f; c[j][3]=0.f; }
        mma_chunk<96>(c, a_base, b_base + (uint32_t)ch * 96 * 208, lane, m0);
        #pragma unroll
        for (int j = 0; j < 12; j++) {
            int col = ch * 96 + j * 8 + (lane & 3) * 2;
            float bi0 = __ldg(bias + col), bi1 = __ldg(bias + col + 1);
            float v0 = c[j][0] + bi0, v1 = c[j][1] + bi1;
            float v2 = c[j][2] + bi0, v3 = c[j][3] + bi1;
            v0 = 0.5f * v0 * (1.0f + erff(v0 * 0.70710678118654752f));
            v1 = 0.5f * v1 * (1.0f + erff(v1 * 0.70710678118654752f));
            v2 = 0.5f * v2 * (1.0f + erff(v2 * 0.70710678118654752f));
            v3 = 0.5f * v3 * (1.0f + erff(v3 * 0.70710678118654752f));
            *(uint32_t*)(g_h + row0 * 384 + col)       = packbf2(v0, v1);
            *(uint32_t*)(g_h + (row0 + 8) * 384 + col) = packbf2(v2, v3);
        }
    }
}

// =====================================================================
// GEMM fc2: [128x384] @ [96x384]^T + bias + residual -> out fp32
// =====================================================================
__global__ __launch_bounds__(256) void gemm_fc2_kernel(
    const float* __restrict__ w, const float* __restrict__ bias, float* __restrict__ out)
{
    extern __shared__ __nv_bfloat16 smh[];
    __nv_bfloat16* As = smh;                 // 128*392
    __nv_bfloat16* Bs = smh + 128 * 392;     // 96*392
    const int tid = threadIdx.x, lane = tid & 31, wid = tid >> 5;
    copy_A<384>(As, g_h + (size_t)blockIdx.x * 128 * 384);
    copy_B<384>(Bs, w, 96);
    __syncthreads();
    const uint32_t a_base = smem_u32(As), b_base = smem_u32(Bs);
    const int m0 = wid * 16;

    float c[12][4];
    #pragma unroll
    for (int j = 0; j < 12; j++) { c[j][0]=0.f; c[j][1]=0.f; c[j][2]=0.f; c[j][3]=0.f; }
    mma_chunk<384>(c, a_base, b_base, lane, m0);

    const size_t row0 = (size_t)blockIdx.x * 128 + m0 + (lane >> 2);
    #pragma unroll
    for (int j = 0; j < 12; j++) {
        int col = j * 8 + (lane & 3) * 2;
        float bi0 = __ldg(bias + col), bi1 = __ldg(bias + col + 1);
        float2 r0 = *(const float2*)(g_x1 + row0 * 96 + col);
        float2 r1 = *(const float2*)(g_x1 + (row0 + 8) * 96 + col);
        *(float2*)(out + row0 * 96 + col)       = make_float2(c[j][0] + bi0 + r0.x, c[j][1] + bi1 + r0.y);
        *(float2*)(out + (row0 + 8) * 96 + col) = make_float2(c[j][2] + bi0 + r1.x, c[j][3] + bi1 + r1.y);
    }
}

// =====================================================================
extern "C" void kernel_launch(void* const* d_in, const int* in_sizes, int n_in,
                              void* d_out, int out_size)
{
    (void)in_sizes; (void)n_in; (void)out_size;
    const float* x      = (const float*)d_in[0];
    const float* mask   = (const float*)d_in[1];
    const float* n1g    = (const float*)d_in[2];
    const float* n1b    = (const float*)d_in[3];
    const float* qkv_w  = (const float*)d_in[4];
    const float* qkv_b  = (const float*)d_in[5];
    const float* proj_w = (const float*)d_in[6];
    const float* proj_b = (const float*)d_in[7];
    const float* n2g    = (const float*)d_in[8];
    const float* n2b    = (const float*)d_in[9];
    const float* fc1_w  = (const float*)d_in[10];
    const float* fc1_b  = (const float*)d_in[11];
    const float* fc2_w  = (const float*)d_in[12];
    const float* fc2_b  = (const float*)d_in[13];
    float* out = (float*)d_out;

    const int smQkv  = (128 * 104 + 288 * 104) * 2;     // 86528
    const int smProj = (128 * 104 + 96 * 104) * 2;      // 46592
    const int smFc1  = (128 * 104 + 384 * 104) * 2;     // 106496
    const int smFc2  = (128 * 392 + 96 * 392) * 2;      // 175616
    const int smAtt  = (NT * QS + 3 * NT * NT) * 4;     // 86044

    cudaFuncSetAttribute(gemm_qkv_kernel,  cudaFuncAttributeMaxDynamicSharedMemorySize, smQkv);
    cudaFuncSetAttribute(gemm_proj_kernel, cudaFuncAttributeMaxDynamicSharedMemorySize, smProj);
    cudaFuncSetAttribute(gemm_fc1_kernel,  cudaFuncAttributeMaxDynamicSharedMemorySize, smFc1);
    cudaFuncSetAttribute(gemm_fc2_kernel,  cudaFuncAttributeMaxDynamicSharedMemorySize, smFc2);
    cudaFuncSetAttribute(attn_core_kernel, cudaFuncAttributeMaxDynamicSharedMemorySize, smAtt);

    ln1_kernel<<<8192, 256>>>(x, n1g, n1b);
    gemm_qkv_kernel<<<MTILES, 256, smQkv>>>(qkv_w, qkv_b);
    attn_core_kernel<<<8192, 256, smAtt>>>(mask);
    gemm_proj_kernel<<<MTILES, 256, smProj>>>(proj_w, proj_b, x, n2g, n2b);
    gemm_fc1_kernel<<<MTILES, 256, smFc1>>>(fc1_w, fc1_b);
    gemm_fc2_kernel<<<MTILES, 256, smFc2>>>(fc2_w, fc2_b, out);
}

// round 4
// speedup vs baseline: 2.7225x; 1.3525x over previous
#include <cuda_runtime.h>
#include <cuda_bf16.h>
#include <stdint.h>
#include <math.h>

#define Hh 224
#define Ww 224
#define NT 49
#define SCALE_Q 0.17677669529663687f
#define LN_EPS 1e-5f
#define NTOKENS (8*224*224)          // 401408
#define MTILES  (NTOKENS/128)        // 3136

__device__ float         g_x1[(size_t)NTOKENS*96];   // x + attn residual (fp32, natural)
__device__ __nv_bfloat16 g_x2[(size_t)NTOKENS*96];   // LN2 out (natural)

// =====================================================================
// helpers
// =====================================================================
__device__ __forceinline__ uint32_t smem_u32(const void* p) {
    uint32_t a;
    asm("{ .reg .u64 t; cvta.to.shared.u64 t, %1; cvt.u32.u64 %0, t; }" : "=r"(a) : "l"(p));
    return a;
}
__device__ __forceinline__ void ldsm4(uint32_t& r0, uint32_t& r1, uint32_t& r2, uint32_t& r3, uint32_t addr) {
    asm volatile("ldmatrix.sync.aligned.m8n8.x4.shared.b16 {%0,%1,%2,%3}, [%4];"
        : "=r"(r0), "=r"(r1), "=r"(r2), "=r"(r3) : "r"(addr));
}
__device__ __forceinline__ void ldsm4t(uint32_t& r0, uint32_t& r1, uint32_t& r2, uint32_t& r3, uint32_t addr) {
    asm volatile("ldmatrix.sync.aligned.m8n8.x4.trans.shared.b16 {%0,%1,%2,%3}, [%4];"
        : "=r"(r0), "=r"(r1), "=r"(r2), "=r"(r3) : "r"(addr));
}
__device__ __forceinline__ void mma16816(float* c, uint32_t a0, uint32_t a1, uint32_t a2, uint32_t a3,
                                         uint32_t b0, uint32_t b1) {
    asm volatile("mma.sync.aligned.m16n8k16.row.col.f32.bf16.bf16.f32 "
        "{%0,%1,%2,%3},{%4,%5,%6,%7},{%8,%9},{%0,%1,%2,%3};"
        : "+f"(c[0]), "+f"(c[1]), "+f"(c[2]), "+f"(c[3])
        : "r"(a0), "r"(a1), "r"(a2), "r"(a3), "r"(b0), "r"(b1));
}
__device__ __forceinline__ uint4 pack8f(const float* p) {
    float4 a = *(const float4*)p, b = *(const float4*)(p + 4);
    __nv_bfloat162 q0 = __floats2bfloat162_rn(a.x, a.y), q1 = __floats2bfloat162_rn(a.z, a.w);
    __nv_bfloat162 q2 = __floats2bfloat162_rn(b.x, b.y), q3 = __floats2bfloat162_rn(b.z, b.w);
    uint4 r;
    r.x = *(uint32_t*)&q0; r.y = *(uint32_t*)&q1; r.z = *(uint32_t*)&q2; r.w = *(uint32_t*)&q3;
    return r;
}
__device__ __forceinline__ uint32_t packbf2(float a, float b) {
    __nv_bfloat162 p = __floats2bfloat162_rn(a, b);
    return *(uint32_t*)&p;
}
// fp32 weights [Nr x K] -> smem bf16, row stride K+8
template <int K>
__device__ __forceinline__ void copy_B(__nv_bfloat16* Bs, const float* w, int Nr) {
    const int C8 = K / 8, S = K + 8;
    for (int i = threadIdx.x; i < Nr * C8; i += blockDim.x) {
        int n = i / C8, c8 = i % C8;
        *(uint4*)(Bs + n * S + c8 * 8) = pack8f(w + n * K + c8 * 8);
    }
}
template <int K>
__device__ __forceinline__ void copy_A(__nv_bfloat16* As, const __nv_bfloat16* a0) {
    const int C8 = K / 8, S = K + 8;
    for (int i = threadIdx.x; i < 128 * C8; i += blockDim.x) {
        int r = i / C8, c8 = i % C8;
        *(uint4*)(As + r * S + c8 * 8) = *(const uint4*)(a0 + (size_t)r * K + c8 * 8);
    }
}
// warp computes 16 rows x 96 cols
template <int K>
__device__ __forceinline__ void mma_chunk(float c[12][4], uint32_t a_base, uint32_t b_base, int lane, int m0) {
    const int SB = (K + 8) * 2;
    uint32_t a_addr = a_base + (uint32_t)(m0 + (lane & 7) + ((lane >> 3) & 1) * 8) * SB + (lane >> 4) * 16;
    uint32_t b_addr = b_base + (uint32_t)((lane & 7) + (lane >> 4) * 8) * SB + ((lane >> 3) & 1) * 16;
    #pragma unroll
    for (int ks = 0; ks < K / 16; ks++) {
        uint32_t a0, a1, a2, a3;
        ldsm4(a0, a1, a2, a3, a_addr + ks * 32);
        #pragma unroll
        for (int j = 0; j < 6; j++) {
            uint32_t b0, b1, b2, b3;
            ldsm4(b0, b1, b2, b3, b_addr + (uint32_t)j * 16 * SB + ks * 32);
            mma16816(c[2 * j],     a0, a1, a2, a3, b0, b1);
            mma16816(c[2 * j + 1], a0, a1, a2, a3, b2, b3);
        }
    }
}

// =====================================================================
// MEGA 1: LN1+gather | qkv | attention (per-head HMMA) | proj+res+LN2
// block = 2 windows (rows: win0 -> 0..48, win1 -> 64..112; pads zero)
// smem: As 128x104 | Qs 128x296 | Bc 96x104 | Ps 128x72  (all bf16)
// =====================================================================
__global__ __launch_bounds__(256) void attn_mega_kernel(
    const float* __restrict__ x, const float* __restrict__ mask,
    const float* __restrict__ n1g, const float* __restrict__ n1b,
    const float* __restrict__ qkv_w, const float* __restrict__ qkv_b,
    const float* __restrict__ proj_w, const float* __restrict__ proj_b,
    const float* __restrict__ n2g, const float* __restrict__ n2b)
{
    extern __shared__ __nv_bfloat16 smh[];
    __nv_bfloat16* As = smh;                               // 128*104
    __nv_bfloat16* Qs = smh + 128 * 104;                   // 128*296
    __nv_bfloat16* Bc = Qs + 128 * 296;                    // 96*104
    __nv_bfloat16* Ps = Bc + 96 * 104;                     // 128*72
    const int tid = threadIdx.x, lane = tid & 31, wid = tid >> 5;
    const int blk = blockIdx.x;

    // ---------- LN1 + shifted window gather ----------
    {
        const float g0 = n1g[lane], g1 = n1g[lane + 32], g2 = n1g[lane + 64];
        const float b0 = n1b[lane], b1 = n1b[lane + 32], b2 = n1b[lane + 64];
        for (int tt = wid; tt < 128; tt += 8) {
            int w2 = tt >> 6, tloc = tt & 63;
            __nv_bfloat16* dst = As + tt * 104;
            if (tloc < NT) {
                int win = blk * 2 + w2;
                int b = win >> 10, wi = (win >> 5) & 31, wj = win & 31;
                int r  = wi * 7 + tloc / 7;
                int cl = wj * 7 + tloc % 7;
                int sr = r + 3;  if (sr >= Hh) sr -= Hh;
                int sc = cl + 3; if (sc >= Ww) sc -= Ww;
                const float* xp = x + ((size_t)(b * Hh + sr) * Ww + sc) * 96;
                float v0 = xp[lane], v1 = xp[lane + 32], v2 = xp[lane + 64];
                float s = v0 + v1 + v2;
                #pragma unroll
                for (int o = 16; o; o >>= 1) s += __shfl_xor_sync(~0u, s, o);
                float mu = s * (1.0f / 96.0f);
                float d0 = v0 - mu, d1 = v1 - mu, d2 = v2 - mu;
                float vs = d0 * d0 + d1 * d1 + d2 * d2;
                #pragma unroll
                for (int o = 16; o; o >>= 1) vs += __shfl_xor_sync(~0u, vs, o);
                float rs = rsqrtf(vs * (1.0f / 96.0f) + LN_EPS);
                dst[lane]      = __float2bfloat16(d0 * rs * g0 + b0);
                dst[lane + 32] = __float2bfloat16(d1 * rs * g1 + b1);
                dst[lane + 64] = __float2bfloat16(d2 * rs * g2 + b2);
            } else {
                __nv_bfloat16 z = __float2bfloat16(0.f);
                dst[lane] = z; dst[lane + 32] = z; dst[lane + 64] = z;
            }
        }
    }
    __syncthreads();

    const uint32_t a_base = smem_u32(As), q_base = smem_u32(Qs);
    const uint32_t b_base = smem_u32(Bc), p_base = smem_u32(Ps);
    const int m0 = wid * 16;

    // ---------- qkv GEMM: 3 chunks of 96 cols, output to Qs smem ----------
    for (int ch = 0; ch < 3; ch++) {
        copy_B<96>(Bc, qkv_w + ch * 96 * 96, 96);
        __syncthreads();
        float c[12][4];
        #pragma unroll
        for (int j = 0; j < 12; j++) { c[j][0]=0.f; c[j][1]=0.f; c[j][2]=0.f; c[j][3]=0.f; }
        mma_chunk<96>(c, a_base, b_base, lane, m0);
        const float qs = (ch == 0) ? SCALE_Q : 1.0f;
        int row0 = m0 + (lane >> 2);
        #pragma unroll
        for (int j = 0; j < 12; j++) {
            int col = ch * 96 + j * 8 + (lane & 3) * 2;
            float bi0 = __ldg(qkv_b + col), bi1 = __ldg(qkv_b + col + 1);
            *(uint32_t*)(Qs + row0 * 296 + col)       = packbf2((c[j][0] + bi0) * qs, (c[j][1] + bi1) * qs);
            *(uint32_t*)(Qs + (row0 + 8) * 296 + col) = packbf2((c[j][2] + bi0) * qs, (c[j][3] + bi1) * qs);
        }
        __syncthreads();
    }

    // ---------- attention, head-sequential ----------
    const int w2 = wid >> 2, mt = wid & 3;     // warp task: rows [w2*64+mt*16, +16)
    const int rbase = w2 * 64 + mt * 16;
    const size_t maskbase = ((size_t)(blk * 2 + w2)) * (NT * NT);
    const int t1 = mt * 16 + (lane >> 2), t2 = t1 + 8;

    for (int h = 0; h < 3; h++) {
        // ---- scores S = q k^T (64x64, K=32) ----
        float c[8][4];
        #pragma unroll
        for (int j = 0; j < 8; j++) { c[j][0]=0.f; c[j][1]=0.f; c[j][2]=0.f; c[j][3]=0.f; }
        uint32_t a_addr = q_base + (uint32_t)(rbase + (lane & 7) + ((lane >> 3) & 1) * 8) * 592 + h * 64 + (lane >> 4) * 16;
        uint32_t b_addr = q_base + (uint32_t)(w2 * 64 + (lane & 7) + (lane >> 4) * 8) * 592 + 192 + h * 64 + ((lane >> 3) & 1) * 16;
        #pragma unroll
        for (int ks = 0; ks < 2; ks++) {
            uint32_t a0, a1, a2, a3;
            ldsm4(a0, a1, a2, a3, a_addr + ks * 32);
            #pragma unroll
            for (int j2 = 0; j2 < 4; j2++) {
                uint32_t b0, b1, b2, b3;
                ldsm4(b0, b1, b2, b3, b_addr + (uint32_t)j2 * 16 * 592 + ks * 32);
                mma16816(c[2 * j2],     a0, a1, a2, a3, b0, b1);
                mma16816(c[2 * j2 + 1], a0, a1, a2, a3, b2, b3);
            }
        }
        // ---- mask + softmax in registers ----
        float mx1 = -1e30f, mx2 = -1e30f;
        #pragma unroll
        for (int j = 0; j < 8; j++) {
            int u = j * 8 + (lane & 3) * 2;
            #pragma unroll
            for (int e = 0; e < 2; e++) {
                int uu = u + e;
                float m1 = (t1 < NT && uu < NT) ? __ldg(mask + maskbase + t1 * NT + uu) : -1e30f;
                float m2 = (t2 < NT && uu < NT) ? __ldg(mask + maskbase + t2 * NT + uu) : -1e30f;
                c[j][e]     += m1;
                c[j][2 + e] += m2;
                mx1 = fmaxf(mx1, c[j][e]);
                mx2 = fmaxf(mx2, c[j][2 + e]);
            }
        }
        mx1 = fmaxf(mx1, __shfl_xor_sync(~0u, mx1, 1)); mx1 = fmaxf(mx1, __shfl_xor_sync(~0u, mx1, 2));
        mx2 = fmaxf(mx2, __shfl_xor_sync(~0u, mx2, 1)); mx2 = fmaxf(mx2, __shfl_xor_sync(~0u, mx2, 2));
        float s1 = 0.f, s2 = 0.f;
        #pragma unroll
        for (int j = 0; j < 8; j++) {
            c[j][0] = __expf(c[j][0] - mx1); c[j][1] = __expf(c[j][1] - mx1);
            c[j][2] = __expf(c[j][2] - mx2); c[j][3] = __expf(c[j][3] - mx2);
            s1 += c[j][0] + c[j][1];
            s2 += c[j][2] + c[j][3];
        }
        s1 += __shfl_xor_sync(~0u, s1, 1); s1 += __shfl_xor_sync(~0u, s1, 2);
        s2 += __shfl_xor_sync(~0u, s2, 1); s2 += __shfl_xor_sync(~0u, s2, 2);
        float i1 = 1.0f / (s1 + 1e-20f), i2 = 1.0f / (s2 + 1e-20f);
        int prow = rbase + (lane >> 2);
        #pragma unroll
        for (int j = 0; j < 8; j++) {
            int u = j * 8 + (lane & 3) * 2;
            *(uint32_t*)(Ps + prow * 72 + u)       = packbf2(c[j][0] * i1, c[j][1] * i1);
            *(uint32_t*)(Ps + (prow + 8) * 72 + u) = packbf2(c[j][2] * i2, c[j][3] * i2);
        }
        __syncthreads();

        // ---- o = P V  (16x32 per warp, K=64) ----
        float c2[4][4];
        #pragma unroll
        for (int n = 0; n < 4; n++) { c2[n][0]=0.f; c2[n][1]=0.f; c2[n][2]=0.f; c2[n][3]=0.f; }
        uint32_t pa = p_base + (uint32_t)(rbase + (lane & 7) + ((lane >> 3) & 1) * 8) * 144 + (lane >> 4) * 16;
        uint32_t vb = q_base + (uint32_t)(w2 * 64 + (lane & 7) + ((lane >> 3) & 1) * 8) * 592 + 384 + h * 64 + (lane >> 4) * 16;
        #pragma unroll
        for (int ks = 0; ks < 4; ks++) {
            uint32_t a0, a1, a2, a3, b0, b1, b2, b3;
            ldsm4(a0, a1, a2, a3, pa + ks * 32);
            ldsm4t(b0, b1, b2, b3, vb + (uint32_t)ks * 16 * 592);
            mma16816(c2[0], a0, a1, a2, a3, b0, b1);
            mma16816(c2[1], a0, a1, a2, a3, b2, b3);
            ldsm4t(b0, b1, b2, b3, vb + (uint32_t)ks * 16 * 592 + 32);
            mma16816(c2[2], a0, a1, a2, a3, b0, b1);
            mma16816(c2[3], a0, a1, a2, a3, b2, b3);
        }
        int row0 = rbase + (lane >> 2);
        #pragma unroll
        for (int n = 0; n < 4; n++) {
            int col = h * 32 + n * 8 + (lane & 3) * 2;
            *(uint32_t*)(As + row0 * 104 + col)       = packbf2(c2[n][0], c2[n][1]);
            *(uint32_t*)(As + (row0 + 8) * 104 + col) = packbf2(c2[n][2], c2[n][3]);
        }
        __syncthreads();
    }

    // ---------- proj + residual + fused LN2 ----------
    copy_B<96>(Bc, proj_w, 96);
    __syncthreads();
    float c[12][4];
    #pragma unroll
    for (int j = 0; j < 12; j++) { c[j][0]=0.f; c[j][1]=0.f; c[j][2]=0.f; c[j][3]=0.f; }
    mma_chunk<96>(c, a_base, b_base, lane, m0);

    size_t nt_[2];
    bool valid[2];
    #pragma unroll
    for (int hh = 0; hh < 2; hh++) {
        int row = m0 + (lane >> 2) + hh * 8;
        int w2r = row >> 6, tloc = row & 63;
        valid[hh] = (tloc < NT);
        int win = blk * 2 + w2r;
        int b = win >> 10, wi = (win >> 5) & 31, wj = win & 31;
        int tl = tloc < NT ? tloc : 0;
        int r  = wi * 7 + tl / 7;
        int cl = wj * 7 + tl % 7;
        int sr = r + 3;  if (sr >= Hh) sr -= Hh;
        int sc = cl + 3; if (sc >= Ww) sc -= Ww;
        nt_[hh] = ((size_t)(b * Hh + sr)) * Ww + sc;
    }
    float s1[2] = {0.f, 0.f}, s2[2] = {0.f, 0.f};
    #pragma unroll
    for (int j = 0; j < 12; j++) {
        int col = j * 8 + (lane & 3) * 2;
        float bi0 = __ldg(proj_b + col), bi1 = __ldg(proj_b + col + 1);
        #pragma unroll
        for (int hh = 0; hh < 2; hh++) {
            float2 xv = valid[hh] ? *(const float2*)(x + nt_[hh] * 96 + col) : make_float2(0.f, 0.f);
            float o0 = c[j][2 * hh]     + bi0 + xv.x;
            float o1 = c[j][2 * hh + 1] + bi1 + xv.y;
            c[j][2 * hh] = o0; c[j][2 * hh + 1] = o1;
            if (valid[hh]) *(float2*)(g_x1 + nt_[hh] * 96 + col) = make_float2(o0, o1);
            s1[hh] += o0 + o1;
            s2[hh] += o0 * o0 + o1 * o1;
        }
    }
    #pragma unroll
    for (int hh = 0; hh < 2; hh++) {
        s1[hh] += __shfl_xor_sync(~0u, s1[hh], 1); s2[hh] += __shfl_xor_sync(~0u, s2[hh], 1);
        s1[hh] += __shfl_xor_sync(~0u, s1[hh], 2); s2[hh] += __shfl_xor_sync(~0u, s2[hh], 2);
    }
    float mu0 = s1[0] * (1.f/96.f), mu1 = s1[1] * (1.f/96.f);
    float rs0 = rsqrtf(s2[0] * (1.f/96.f) - mu0 * mu0 + LN_EPS);
    float rs1 = rsqrtf(s2[1] * (1.f/96.f) - mu1 * mu1 + LN_EPS);
    #pragma unroll
    for (int j = 0; j < 12; j++) {
        int col = j * 8 + (lane & 3) * 2;
        float gg0 = __ldg(n2g + col), gg1 = __ldg(n2g + col + 1);
        float nb0 = __ldg(n2b + col), nb1 = __ldg(n2b + col + 1);
        if (valid[0])
            *(uint32_t*)(g_x2 + nt_[0] * 96 + col) =
                packbf2((c[j][0] - mu0) * rs0 * gg0 + nb0, (c[j][1] - mu0) * rs0 * gg1 + nb1);
        if (valid[1])
            *(uint32_t*)(g_x2 + nt_[1] * 96 + col) =
                packbf2((c[j][2] - mu1) * rs1 * gg0 + nb0, (c[j][3] - mu1) * rs1 * gg1 + nb1);
    }
}

// =====================================================================
// MEGA 2: fc1 + GELU (H in smem) + fc2 + residual -> out
// smem: As 128x104 | Hs 128x392 | Bc (96x104 fc1-chunk / 96x392 fc2)
// =====================================================================
__global__ __launch_bounds__(256) void mlp_mega_kernel(
    const float* __restrict__ fc1_w, const float* __restrict__ fc1_b,
    const float* __restrict__ fc2_w, const float* __restrict__ fc2_b,
    float* __restrict__ out)
{
    extern __shared__ __nv_bfloat16 smh[];
    __nv_bfloat16* As = smh;                       // 128*104
    __nv_bfloat16* Hs = smh + 128 * 104;           // 128*392
    __nv_bfloat16* Bc = Hs + 128 * 392;            // up to 96*392
    const int tid = threadIdx.x, lane = tid & 31, wid = tid >> 5;
    const int m0 = wid * 16;

    copy_A<96>(As, g_x2 + (size_t)blockIdx.x * 128 * 96);
    __syncthreads();
    const uint32_t a_base = smem_u32(As), h_base = smem_u32(Hs), b_base = smem_u32(Bc);

    // fc1: 4 chunks of 96 cols -> Hs (stride 392)
    for (int ch = 0; ch < 4; ch++) {
        copy_B<96>(Bc, fc1_w + ch * 96 * 96, 96);
        __syncthreads();
        float c[12][4];
        #pragma unroll
        for (int j = 0; j < 12; j++) { c[j][0]=0.f; c[j][1]=0.f; c[j][2]=0.f; c[j][3]=0.f; }
        mma_chunk<96>(c, a_base, b_base, lane, m0);
        int row0 = m0 + (lane >> 2);
        #pragma unroll
        for (int j = 0; j < 12; j++) {
            int col = ch * 96 + j * 8 + (lane & 3) * 2;
            float bi0 = __ldg(fc1_b + col), bi1 = __ldg(fc1_b + col + 1);
            float v0 = c[j][0] + bi0, v1 = c[j][1] + bi1;
            float v2 = c[j][2] + bi0, v3 = c[j][3] + bi1;
            v0 = 0.5f * v0 * (1.0f + erff(v0 * 0.70710678118654752f));
            v1 = 0.5f * v1 * (1.0f + erff(v1 * 0.70710678118654752f));
            v2 = 0.5f * v2 * (1.0f + erff(v2 * 0.70710678118654752f));
            v3 = 0.5f * v3 * (1.0f + erff(v3 * 0.70710678118654752f));
            *(uint32_t*)(Hs + row0 * 392 + col)       = packbf2(v0, v1);
            *(uint32_t*)(Hs + (row0 + 8) * 392 + col) = packbf2(v2, v3);
        }
        __syncthreads();
    }

    // fc2: K=384 from Hs, B = fc2_w (96x384)
    copy_B<384>(Bc, fc2_w, 96);
    __syncthreads();
    float c[12][4];
    #pragma unroll
    for (int j = 0; j < 12; j++) { c[j][0]=0.f; c[j][1]=0.f; c[j][2]=0.f; c[j][3]=0.f; }
    mma_chunk<384>(c, h_base, b_base, lane, m0);

    const size_t row0 = (size_t)blockIdx.x * 128 + m0 + (lane >> 2);
    #pragma unroll
    for (int j = 0; j < 12; j++) {
        int col = j * 8 + (lane & 3) * 2;
        float bi0 = __ldg(fc2_b + col), bi1 = __ldg(fc2_b + col + 1);
        float2 r0 = *(const float2*)(g_x1 + row0 * 96 + col);
        float2 r1 = *(const float2*)(g_x1 + (row0 + 8) * 96 + col);
        *(float2*)(out + row0 * 96 + col)       = make_float2(c[j][0] + bi0 + r0.x, c[j][1] + bi1 + r0.y);
        *(float2*)(out + (row0 + 8) * 96 + col) = make_float2(c[j][2] + bi0 + r1.x, c[j][3] + bi1 + r1.y);
    }
}

// =====================================================================
extern "C" void kernel_launch(void* const* d_in, const int* in_sizes, int n_in,
                              void* d_out, int out_size)
{
    (void)in_sizes; (void)n_in; (void)out_size;
    const float* x      = (const float*)d_in[0];
    const float* mask   = (const float*)d_in[1];
    const float* n1g    = (const float*)d_in[2];
    const float* n1b    = (const float*)d_in[3];
    const float* qkv_w  = (const float*)d_in[4];
    const float* qkv_b  = (const float*)d_in[5];
    const float* proj_w = (const float*)d_in[6];
    const float* proj_b = (const float*)d_in[7];
    const float* n2g    = (const float*)d_in[8];
    const float* n2b    = (const float*)d_in[9];
    const float* fc1_w  = (const float*)d_in[10];
    const float* fc1_b  = (const float*)d_in[11];
    const float* fc2_w  = (const float*)d_in[12];
    const float* fc2_b  = (const float*)d_in[13];
    float* out = (float*)d_out;

    const int smAttn = (128*104 + 128*296 + 96*104 + 128*72) * 2;   // 140800
    const int smMlp  = (128*104 + 128*392 + 96*392) * 2;            // 202240

    cudaFuncSetAttribute(attn_mega_kernel, cudaFuncAttributeMaxDynamicSharedMemorySize, smAttn);
    cudaFuncSetAttribute(mlp_mega_kernel,  cudaFuncAttributeMaxDynamicSharedMemorySize, smMlp);

    attn_mega_kernel<<<4096, 256, smAttn>>>(x, mask, n1g, n1b, qkv_w, qkv_b,
                                            proj_w, proj_b, n2g, n2b);
    mlp_mega_kernel<<<MTILES, 256, smMlp>>>(fc1_w, fc1_b, fc2_w, fc2_b, out);
}

// round 5
// speedup vs baseline: 3.7965x; 1.3945x over previous
#include <cuda_runtime.h>
#include <cuda_bf16.h>
#include <stdint.h>
#include <math.h>

#define Hh 224
#define Ww 224
#define NT 49
#define SCALE_Q 0.17677669529663687f
#define LN_EPS 1e-5f
#define NTOKENS (8*224*224)          // 401408
#define MTILES  (NTOKENS/128)        // 3136

// fp32/bf16 activation scratch
__device__ float         g_x1[(size_t)NTOKENS*96];   // x + attn residual (natural)
__device__ __nv_bfloat16 g_x2[(size_t)NTOKENS*96];   // LN2 out (natural)
__device__ __nv_bfloat16 g_h [(size_t)NTOKENS*384];  // fc1+GELU out

// pre-swizzled bf16 weights (row stride 104, smem-ready)
__device__ __nv_bfloat16 g_wq[288*104];
__device__ __nv_bfloat16 g_wp[96*104];
__device__ __nv_bfloat16 g_w1[384*104];
__device__ __nv_bfloat16 g_w2[4][96*104];            // fc2 K-chunks

// =====================================================================
// helpers
// =====================================================================
__device__ __forceinline__ uint32_t smem_u32(const void* p) {
    uint32_t a;
    asm("{ .reg .u64 t; cvta.to.shared.u64 t, %1; cvt.u32.u64 %0, t; }" : "=r"(a) : "l"(p));
    return a;
}
__device__ __forceinline__ void ldsm4(uint32_t& r0, uint32_t& r1, uint32_t& r2, uint32_t& r3, uint32_t addr) {
    asm volatile("ldmatrix.sync.aligned.m8n8.x4.shared.b16 {%0,%1,%2,%3}, [%4];"
        : "=r"(r0), "=r"(r1), "=r"(r2), "=r"(r3) : "r"(addr));
}
__device__ __forceinline__ void ldsm4t(uint32_t& r0, uint32_t& r1, uint32_t& r2, uint32_t& r3, uint32_t addr) {
    asm volatile("ldmatrix.sync.aligned.m8n8.x4.trans.shared.b16 {%0,%1,%2,%3}, [%4];"
        : "=r"(r0), "=r"(r1), "=r"(r2), "=r"(r3) : "r"(addr));
}
__device__ __forceinline__ void mma16816(float* c, uint32_t a0, uint32_t a1, uint32_t a2, uint32_t a3,
                                         uint32_t b0, uint32_t b1) {
    asm volatile("mma.sync.aligned.m16n8k16.row.col.f32.bf16.bf16.f32 "
        "{%0,%1,%2,%3},{%4,%5,%6,%7},{%8,%9},{%0,%1,%2,%3};"
        : "+f"(c[0]), "+f"(c[1]), "+f"(c[2]), "+f"(c[3])
        : "r"(a0), "r"(a1), "r"(a2), "r"(a3), "r"(b0), "r"(b1));
}
__device__ __forceinline__ uint32_t packbf2(float a, float b) {
    __nv_bfloat162 p = __floats2bfloat162_rn(a, b);
    return *(uint32_t*)&p;
}
// warp GEMM: 16 rows x 96 cols, K=96. SAE/SBE = element strides.
template <int SAE, int SBE>
__device__ __forceinline__ void wgemm_16x96(float c[12][4], uint32_t a_base, uint32_t b_base,
                                            int lane, int row0) {
    const int SA = SAE * 2, SB = SBE * 2;
    uint32_t a_addr = a_base + (uint32_t)(row0 + (lane & 7) + ((lane >> 3) & 1) * 8) * SA + (lane >> 4) * 16;
    uint32_t b_addr = b_base + (uint32_t)((lane & 7) + (lane >> 4) * 8) * SB + ((lane >> 3) & 1) * 16;
    #pragma unroll
    for (int ks = 0; ks < 6; ks++) {
        uint32_t a0, a1, a2, a3;
        ldsm4(a0, a1, a2, a3, a_addr + ks * 32);
        #pragma unroll
        for (int j = 0; j < 6; j++) {
            uint32_t b0, b1, b2, b3;
            ldsm4(b0, b1, b2, b3, b_addr + (uint32_t)j * 16 * SB + ks * 32);
            mma16816(c[2 * j],     a0, a1, a2, a3, b0, b1);
            mma16816(c[2 * j + 1], a0, a1, a2, a3, b2, b3);
        }
    }
}
// warp GEMM: 16 rows x 48 cols, K=96
template <int SAE, int SBE>
__device__ __forceinline__ void wgemm_16x48(float c[6][4], uint32_t a_base, uint32_t b_base,
                                            int lane, int row0, int ncol0) {
    const int SA = SAE * 2, SB = SBE * 2;
    uint32_t a_addr = a_base + (uint32_t)(row0 + (lane & 7) + ((lane >> 3) & 1) * 8) * SA + (lane >> 4) * 16;
    uint32_t b_addr = b_base + (uint32_t)(ncol0 + (lane & 7) + (lane >> 4) * 8) * SB + ((lane >> 3) & 1) * 16;
    #pragma unroll
    for (int ks = 0; ks < 6; ks++) {
        uint32_t a0, a1, a2, a3;
        ldsm4(a0, a1, a2, a3, a_addr + ks * 32);
        #pragma unroll
        for (int j = 0; j < 3; j++) {
            uint32_t b0, b1, b2, b3;
            ldsm4(b0, b1, b2, b3, b_addr + (uint32_t)j * 16 * SB + ks * 32);
            mma16816(c[2 * j],     a0, a1, a2, a3, b0, b1);
            mma16816(c[2 * j + 1], a0, a1, a2, a3, b2, b3);
        }
    }
}

// =====================================================================
// weight pre-swizzle: fp32 -> bf16 tiles, row stride 104
// =====================================================================
__global__ __launch_bounds__(256) void prep_weights(
    const float* __restrict__ qkv_w, const float* __restrict__ proj_w,
    const float* __restrict__ fc1_w, const float* __restrict__ fc2_w)
{
    int i = blockIdx.x * 256 + threadIdx.x;
    if (i >= 1152 * 96) return;
    int row = i / 96, col = i % 96;
    float v; __nv_bfloat16* dst;
    if (row < 288)      { v = qkv_w[row * 96 + col];               dst = g_wq + row * 104 + col; }
    else if (row < 384) { int r = row - 288; v = proj_w[r * 96 + col]; dst = g_wp + r * 104 + col; }
    else if (row < 768) { int r = row - 384; v = fc1_w[r * 96 + col];  dst = g_w1 + r * 104 + col; }
    else { int r = row - 768; int kc = r / 96, n = r % 96;
           v = fc2_w[n * 384 + kc * 96 + col]; dst = g_w2[kc] + n * 104 + col; }
    *dst = __float2bfloat16(v);
}

// =====================================================================
// ATTN: 1 window / block, 256 threads, 3 CTAs/SM
// smem: As 64x104 | Qs 64x296 (Q|K|V; o overwrites Q) | Bc 96x104
// =====================================================================
__global__ __launch_bounds__(256, 3) void attn_kernel(
    const float* __restrict__ x, const float* __restrict__ mask,
    const float* __restrict__ n1g, const float* __restrict__ n1b,
    const float* __restrict__ qkv_b, const float* __restrict__ proj_b,
    const float* __restrict__ n2g, const float* __restrict__ n2b)
{
    extern __shared__ char smraw[];
    __nv_bfloat16* As = (__nv_bfloat16*)smraw;              // 64*104
    __nv_bfloat16* Qs = (__nv_bfloat16*)(smraw + 13312);    // 64*296
    __nv_bfloat16* Bc = (__nv_bfloat16*)(smraw + 51200);    // 96*104
    const int tid = threadIdx.x, lane = tid & 31, wid = tid >> 5;
    const int blk = blockIdx.x;
    const int bI = blk >> 10, wi = (blk >> 5) & 31, wj = blk & 31;

    // ---------- LN1 + shifted gather ----------
    {
        const float g0 = n1g[lane], g1 = n1g[lane + 32], g2 = n1g[lane + 64];
        const float b0 = n1b[lane], b1 = n1b[lane + 32], b2 = n1b[lane + 64];
        for (int t = wid; t < 64; t += 8) {
            __nv_bfloat16* dst = As + t * 104;
            if (t < NT) {
                int r  = wi * 7 + t / 7;
                int cl = wj * 7 + t % 7;
                int sr = r + 3;  if (sr >= Hh) sr -= Hh;
                int sc = cl + 3; if (sc >= Ww) sc -= Ww;
                const float* xp = x + ((size_t)(bI * Hh + sr) * Ww + sc) * 96;
                float v0 = xp[lane], v1 = xp[lane + 32], v2 = xp[lane + 64];
                float s = v0 + v1 + v2;
                #pragma unroll
                for (int o = 16; o; o >>= 1) s += __shfl_xor_sync(~0u, s, o);
                float mu = s * (1.0f / 96.0f);
                float d0 = v0 - mu, d1 = v1 - mu, d2 = v2 - mu;
                float vs = d0 * d0 + d1 * d1 + d2 * d2;
                #pragma unroll
                for (int o = 16; o; o >>= 1) vs += __shfl_xor_sync(~0u, vs, o);
                float rs = rsqrtf(vs * (1.0f / 96.0f) + LN_EPS);
                dst[lane]      = __float2bfloat16(d0 * rs * g0 + b0);
                dst[lane + 32] = __float2bfloat16(d1 * rs * g1 + b1);
                dst[lane + 64] = __float2bfloat16(d2 * rs * g2 + b2);
            } else {
                __nv_bfloat16 z = __float2bfloat16(0.f);
                dst[lane] = z; dst[lane + 32] = z; dst[lane + 64] = z;
            }
        }
    }
    __syncthreads();

    const uint32_t a_base = smem_u32(As), q_base = smem_u32(Qs), b_base = smem_u32(Bc);
    const int rt4 = wid >> 1, ch48 = (wid & 1) * 48;   // GEMM warp grid 4x2

    // ---------- qkv: 3 chunks of 96 cols -> Qs ----------
    for (int ch = 0; ch < 3; ch++) {
        if (ch) __syncthreads();
        {   // flat copy of pre-swizzled chunk (96*104 bf16 = 1248 uint4)
            const uint4* src = (const uint4*)(g_wq + ch * 96 * 104);
            uint4* dst = (uint4*)Bc;
            for (int i = tid; i < 1248; i += 256) dst[i] = src[i];
        }
        __syncthreads();
        float c[6][4];
        #pragma unroll
        for (int j = 0; j < 6; j++) { c[j][0]=0.f; c[j][1]=0.f; c[j][2]=0.f; c[j][3]=0.f; }
        wgemm_16x48<104, 104>(c, a_base, b_base, lane, rt4 * 16, ch48);
        const float qs = (ch == 0) ? SCALE_Q : 1.0f;
        int row0 = rt4 * 16 + (lane >> 2);
        #pragma unroll
        for (int j = 0; j < 6; j++) {
            int jc = ch * 96 + ch48 + j * 8 + (lane & 3) * 2;
            float bi0 = __ldg(qkv_b + jc), bi1 = __ldg(qkv_b + jc + 1);
            *(uint32_t*)(Qs + row0 * 296 + jc)       = packbf2((c[j][0] + bi0) * qs, (c[j][1] + bi1) * qs);
            *(uint32_t*)(Qs + (row0 + 8) * 296 + jc) = packbf2((c[j][2] + bi0) * qs, (c[j][3] + bi1) * qs);
        }
    }
    __syncthreads();

    // prefetch proj weights into Bc (free during attention)
    {
        const uint4* src = (const uint4*)g_wp;
        uint4* dst = (uint4*)Bc;
        for (int i = tid; i < 1248; i += 256) dst[i] = src[i];
    }

    // ---------- attention: barrier-free, P in registers ----------
    const size_t mb = (size_t)blk * (NT * NT);
    for (int task = wid; task < 12; task += 8) {
        int h = task >> 2, rt = task & 3;
        float c[8][4];
        #pragma unroll
        for (int j = 0; j < 8; j++) { c[j][0]=0.f; c[j][1]=0.f; c[j][2]=0.f; c[j][3]=0.f; }
        uint32_t a_addr = q_base + (uint32_t)(rt * 16 + (lane & 7) + ((lane >> 3) & 1) * 8) * 592 + h * 64 + (lane >> 4) * 16;
        uint32_t b_addr = q_base + (uint32_t)((lane & 7) + (lane >> 4) * 8) * 592 + 192 + h * 64 + ((lane >> 3) & 1) * 16;
        #pragma unroll
        for (int ks = 0; ks < 2; ks++) {
            uint32_t a0, a1, a2, a3;
            ldsm4(a0, a1, a2, a3, a_addr + ks * 32);
            #pragma unroll
            for (int j2 = 0; j2 < 4; j2++) {
                uint32_t b0, b1, b2, b3;
                ldsm4(b0, b1, b2, b3, b_addr + (uint32_t)j2 * 16 * 592 + ks * 32);
                mma16816(c[2 * j2],     a0, a1, a2, a3, b0, b1);
                mma16816(c[2 * j2 + 1], a0, a1, a2, a3, b2, b3);
            }
        }
        int t1 = rt * 16 + (lane >> 2), t2 = t1 + 8;
        bool v1 = t1 < NT, v2 = t2 < NT;
        float mx1 = -1e30f, mx2 = -1e30f;
        #pragma unroll
        for (int j = 0; j < 8; j++) {
            #pragma unroll
            for (int e = 0; e < 2; e++) {
                int u = j * 8 + (lane & 3) * 2 + e;
                float m1 = (v1 && u < NT) ? __ldg(mask + mb + t1 * NT + u) : -1e30f;
                float m2 = (v2 && u < NT) ? __ldg(mask + mb + t2 * NT + u) : -1e30f;
                c[j][e]     += m1; c[j][2 + e] += m2;
                mx1 = fmaxf(mx1, c[j][e]);
                mx2 = fmaxf(mx2, c[j][2 + e]);
            }
        }
        mx1 = fmaxf(mx1, __shfl_xor_sync(~0u, mx1, 1)); mx1 = fmaxf(mx1, __shfl_xor_sync(~0u, mx1, 2));
        mx2 = fmaxf(mx2, __shfl_xor_sync(~0u, mx2, 1)); mx2 = fmaxf(mx2, __shfl_xor_sync(~0u, mx2, 2));
        float s1 = 0.f, s2 = 0.f;
        #pragma unroll
        for (int j = 0; j < 8; j++) {
            c[j][0] = __expf(c[j][0] - mx1); c[j][1] = __expf(c[j][1] - mx1);
            c[j][2] = __expf(c[j][2] - mx2); c[j][3] = __expf(c[j][3] - mx2);
            s1 += c[j][0] + c[j][1]; s2 += c[j][2] + c[j][3];
        }
        s1 += __shfl_xor_sync(~0u, s1, 1); s1 += __shfl_xor_sync(~0u, s1, 2);
        s2 += __shfl_xor_sync(~0u, s2, 1); s2 += __shfl_xor_sync(~0u, s2, 2);
        float i1 = 1.0f / (s1 + 1e-20f), i2 = 1.0f / (s2 + 1e-20f);
        // C-frag -> A-frag conversion (P never leaves registers)
        uint32_t ap[4][4];
        #pragma unroll
        for (int s = 0; s < 4; s++) {
            ap[s][0] = packbf2(c[2*s][0]   * i1, c[2*s][1]   * i1);
            ap[s][1] = packbf2(c[2*s][2]   * i2, c[2*s][3]   * i2);
            ap[s][2] = packbf2(c[2*s+1][0] * i1, c[2*s+1][1] * i1);
            ap[s][3] = packbf2(c[2*s+1][2] * i2, c[2*s+1][3] * i2);
        }
        // o = P V  (16x32), V via ldsm.trans
        float c2[4][4];
        #pragma unroll
        for (int n = 0; n < 4; n++) { c2[n][0]=0.f; c2[n][1]=0.f; c2[n][2]=0.f; c2[n][3]=0.f; }
        uint32_t vb = q_base + (uint32_t)((lane & 7) + ((lane >> 3) & 1) * 8) * 592 + 384 + h * 64 + (lane >> 4) * 16;
        #pragma unroll
        for (int ks = 0; ks < 4; ks++) {
            uint32_t b0, b1, b2, b3;
            ldsm4t(b0, b1, b2, b3, vb + (uint32_t)ks * 16 * 592);
            mma16816(c2[0], ap[ks][0], ap[ks][1], ap[ks][2], ap[ks][3], b0, b1);
            mma16816(c2[1], ap[ks][0], ap[ks][1], ap[ks][2], ap[ks][3], b2, b3);
            ldsm4t(b0, b1, b2, b3, vb + (uint32_t)ks * 16 * 592 + 32);
            mma16816(c2[2], ap[ks][0], ap[ks][1], ap[ks][2], ap[ks][3], b0, b1);
            mma16816(c2[3], ap[ks][0], ap[ks][1], ap[ks][2], ap[ks][3], b2, b3);
        }
        // o overwrites this warp's own Q columns in place
        int row = rt * 16 + (lane >> 2);
        #pragma unroll
        for (int n = 0; n < 4; n++) {
            int col = h * 32 + n * 8 + (lane & 3) * 2;
            *(uint32_t*)(Qs + row * 296 + col)       = packbf2(c2[n][0], c2[n][1]);
            *(uint32_t*)(Qs + (row + 8) * 296 + col) = packbf2(c2[n][2], c2[n][3]);
        }
    }
    __syncthreads();

    // ---------- proj (+bias +residual +fused LN2) ----------
    float c[6][4];
    #pragma unroll
    for (int j = 0; j < 6; j++) { c[j][0]=0.f; c[j][1]=0.f; c[j][2]=0.f; c[j][3]=0.f; }
    wgemm_16x48<296, 104>(c, q_base, b_base, lane, rt4 * 16, ch48);

    int r1 = rt4 * 16 + (lane >> 2), r2 = r1 + 8;
    bool va = r1 < NT, vb2 = r2 < NT;
    size_t nt1 = 0, nt2 = 0;
    {
        int tl = va ? r1 : 0;
        int r = wi * 7 + tl / 7, cl = wj * 7 + tl % 7;
        int sr = r + 3;  if (sr >= Hh) sr -= Hh;
        int sc = cl + 3; if (sc >= Ww) sc -= Ww;
        nt1 = ((size_t)(bI * Hh + sr)) * Ww + sc;
        tl = vb2 ? r2 : 0;
        r = wi * 7 + tl / 7; cl = wj * 7 + tl % 7;
        sr = r + 3;  if (sr >= Hh) sr -= Hh;
        sc = cl + 3; if (sc >= Ww) sc -= Ww;
        nt2 = ((size_t)(bI * Hh + sr)) * Ww + sc;
    }
    float s1a = 0.f, s2a = 0.f, s1b = 0.f, s2b = 0.f;
    #pragma unroll
    for (int j = 0; j < 6; j++) {
        int col = ch48 + j * 8 + (lane & 3) * 2;
        float bi0 = __ldg(proj_b + col), bi1 = __ldg(proj_b + col + 1);
        float2 xa = va  ? *(const float2*)(x + nt1 * 96 + col) : make_float2(0.f, 0.f);
        float2 xb = vb2 ? *(const float2*)(x + nt2 * 96 + col) : make_float2(0.f, 0.f);
        float o0 = c[j][0] + bi0 + xa.x, o1 = c[j][1] + bi1 + xa.y;
        float o2 = c[j][2] + bi0 + xb.x, o3 = c[j][3] + bi1 + xb.y;
        c[j][0] = o0; c[j][1] = o1; c[j][2] = o2; c[j][3] = o3;
        if (va)  *(float2*)(g_x1 + nt1 * 96 + col) = make_float2(o0, o1);
        if (vb2) *(float2*)(g_x1 + nt2 * 96 + col) = make_float2(o2, o3);
        s1a += o0 + o1; s2a += o0 * o0 + o1 * o1;
        s1b += o2 + o3; s2b += o2 * o2 + o3 * o3;
    }
    s1a += __shfl_xor_sync(~0u, s1a, 1); s1a += __shfl_xor_sync(~0u, s1a, 2);
    s2a += __shfl_xor_sync(~0u, s2a, 1); s2a += __shfl_xor_sync(~0u, s2a, 2);
    s1b += __shfl_xor_sync(~0u, s1b, 1); s1b += __shfl_xor_sync(~0u, s1b, 2);
    s2b += __shfl_xor_sync(~0u, s2b, 1); s2b += __shfl_xor_sync(~0u, s2b, 2);
    float* red = (float*)As;    // [64][2] sums, [64][2] sq — As is dead
    if ((lane & 3) == 0) {
        red[r1 * 2 + (wid & 1)]       = s1a; red[128 + r1 * 2 + (wid & 1)] = s2a;
        red[r2 * 2 + (wid & 1)]       = s1b; red[128 + r2 * 2 + (wid & 1)] = s2b;
    }
    __syncthreads();
    float mu1 = (red[r1 * 2] + red[r1 * 2 + 1]) * (1.f / 96.f);
    float mu2 = (red[r2 * 2] + red[r2 * 2 + 1]) * (1.f / 96.f);
    float rs1 = rsqrtf((red[128 + r1 * 2] + red[128 + r1 * 2 + 1]) * (1.f / 96.f) - mu1 * mu1 + LN_EPS);
    float rs2 = rsqrtf((red[128 + r2 * 2] + red[128 + r2 * 2 + 1]) * (1.f / 96.f) - mu2 * mu2 + LN_EPS);
    #pragma unroll
    for (int j = 0; j < 6; j++) {
        int col = ch48 + j * 8 + (lane & 3) * 2;
        float gg0 = __ldg(n2g + col), gg1 = __ldg(n2g + col + 1);
        float nb0 = __ldg(n2b + col), nb1 = __ldg(n2b + col + 1);
        if (va)
            *(uint32_t*)(g_x2 + nt1 * 96 + col) =
                packbf2((c[j][0] - mu1) * rs1 * gg0 + nb0, (c[j][1] - mu1) * rs1 * gg1 + nb1);
        if (vb2)
            *(uint32_t*)(g_x2 + nt2 * 96 + col) =
                packbf2((c[j][2] - mu2) * rs2 * gg0 + nb0, (c[j][3] - mu2) * rs2 * gg1 + nb1);
    }
}

// =====================================================================
// fc1: B fully resident (80KB), ONE barrier, 4 chunks back-to-back
// smem: As 128x104 | Bs 384x104  (106.5KB -> 2 CTAs/SM)
// =====================================================================
__global__ __launch_bounds__(256, 2) void fc1_kernel(const float* __restrict__ bias)
{
    extern __shared__ char smraw[];
    __nv_bfloat16* As = (__nv_bfloat16*)smraw;             // 128*104
    __nv_bfloat16* Bs = (__nv_bfloat16*)(smraw + 26624);   // 384*104
    const int tid = threadIdx.x, lane = tid & 31, wid = tid >> 5;
    {
        const __nv_bfloat16* a0 = g_x2 + (size_t)blockIdx.x * 128 * 96;
        for (int i = tid; i < 128 * 12; i += 256) {
            int r = i / 12, c8 = i % 12;
            *(uint4*)(As + r * 104 + c8 * 8) = *(const uint4*)(a0 + (size_t)r * 96 + c8 * 8);
        }
        const uint4* src = (const uint4*)g_w1;
        uint4* dst = (uint4*)Bs;
        for (int i = tid; i < 4992; i += 256) dst[i] = src[i];
    }
    __syncthreads();
    const uint32_t a_base = smem_u32(As), b_base = smem_u32(Bs);
    const int m0 = wid * 16;
    const size_t row0 = (size_t)blockIdx.x * 128 + m0 + (lane >> 2);
    for (int ch = 0; ch < 4; ch++) {
        float c[12][4];
        #pragma unroll
        for (int j = 0; j < 12; j++) { c[j][0]=0.f; c[j][1]=0.f; c[j][2]=0.f; c[j][3]=0.f; }
        wgemm_16x96<104, 104>(c, a_base, b_base + (uint32_t)ch * 96 * 208, lane, m0);
        #pragma unroll
        for (int j = 0; j < 12; j++) {
            int col = ch * 96 + j * 8 + (lane & 3) * 2;
            float bi0 = __ldg(bias + col), bi1 = __ldg(bias + col + 1);
            float v0 = c[j][0] + bi0, v1 = c[j][1] + bi1;
            float v2 = c[j][2] + bi0, v3 = c[j][3] + bi1;
            v0 = 0.5f * v0 * (1.0f + erff(v0 * 0.70710678118654752f));
            v1 = 0.5f * v1 * (1.0f + erff(v1 * 0.70710678118654752f));
            v2 = 0.5f * v2 * (1.0f + erff(v2 * 0.70710678118654752f));
            v3 = 0.5f * v3 * (1.0f + erff(v3 * 0.70710678118654752f));
            *(uint32_t*)(g_h + row0 * 384 + col)       = packbf2(v0, v1);
            *(uint32_t*)(g_h + (row0 + 8) * 384 + col) = packbf2(v2, v3);
        }
    }
}

// =====================================================================
// fc2: K=384 chunked accumulate, smem 46.6KB -> 3 CTAs/SM
// =====================================================================
__global__ __launch_bounds__(256, 3) void fc2_kernel(const float* __restrict__ bias,
                                                     float* __restrict__ out)
{
    extern __shared__ char smraw[];
    __nv_bfloat16* As = (__nv_bfloat16*)smraw;             // 128*104
    __nv_bfloat16* Bs = (__nv_bfloat16*)(smraw + 26624);   // 96*104
    const int tid = threadIdx.x, lane = tid & 31, wid = tid >> 5;
    const int m0 = wid * 16;
    const uint32_t a_base = smem_u32(As), b_base = smem_u32(Bs);

    float c[12][4];
    #pragma unroll
    for (int j = 0; j < 12; j++) { c[j][0]=0.f; c[j][1]=0.f; c[j][2]=0.f; c[j][3]=0.f; }

    for (int kc = 0; kc < 4; kc++) {
        if (kc) __syncthreads();
        const __nv_bfloat16* a0 = g_h + (size_t)blockIdx.x * 128 * 384 + kc * 96;
        for (int i = tid; i < 128 * 12; i += 256) {
            int r = i / 12, c8 = i % 12;
            *(uint4*)(As + r * 104 + c8 * 8) = *(const uint4*)(a0 + (size_t)r * 384 + c8 * 8);
        }
        const uint4* src = (const uint4*)(g_w2[kc]);
        uint4* dst = (uint4*)Bs;
        for (int i = tid; i < 1248; i += 256) dst[i] = src[i];
        __syncthreads();
        wgemm_16x96<104, 104>(c, a_base, b_base, lane, m0);
    }
    const size_t row0 = (size_t)blockIdx.x * 128 + m0 + (lane >> 2);
    #pragma unroll
    for (int j = 0; j < 12; j++) {
        int col = j * 8 + (lane & 3) * 2;
        float bi0 = __ldg(bias + col), bi1 = __ldg(bias + col + 1);
        float2 r0 = *(const float2*)(g_x1 + row0 * 96 + col);
        float2 r1 = *(const float2*)(g_x1 + (row0 + 8) * 96 + col);
        *(float2*)(out + row0 * 96 + col)       = make_float2(c[j][0] + bi0 + r0.x, c[j][1] + bi1 + r0.y);
        *(float2*)(out + (row0 + 8) * 96 + col) = make_float2(c[j][2] + bi0 + r1.x, c[j][3] + bi1 + r1.y);
    }
}

// =====================================================================
extern "C" void kernel_launch(void* const* d_in, const int* in_sizes, int n_in,
                              void* d_out, int out_size)
{
    (void)in_sizes; (void)n_in; (void)out_size;
    const float* x      = (const float*)d_in[0];
    const float* mask   = (const float*)d_in[1];
    const float* n1g    = (const float*)d_in[2];
    const float* n1b    = (const float*)d_in[3];
    const float* qkv_w  = (const float*)d_in[4];
    const float* qkv_b  = (const float*)d_in[5];
    const float* proj_w = (const float*)d_in[6];
    const float* proj_b = (const float*)d_in[7];
    const float* n2g    = (const float*)d_in[8];
    const float* n2b    = (const float*)d_in[9];
    const float* fc1_w  = (const float*)d_in[10];
    const float* fc1_b  = (const float*)d_in[11];
    const float* fc2_w  = (const float*)d_in[12];
    const float* fc2_b  = (const float*)d_in[13];
    float* out = (float*)d_out;

    const int smAttn = 71168;
    const int smFc1  = 26624 + 79872;   // 106496
    const int smFc2  = 26624 + 19968;   // 46592

    cudaFuncSetAttribute(attn_kernel, cudaFuncAttributeMaxDynamicSharedMemorySize, smAttn);
    cudaFuncSetAttribute(fc1_kernel,  cudaFuncAttributeMaxDynamicSharedMemorySize, smFc1);
    cudaFuncSetAttribute(fc2_kernel,  cudaFuncAttributeMaxDynamicSharedMemorySize, smFc2);

    prep_weights<<<432, 256>>>(qkv_w, proj_w, fc1_w, fc2_w);
    attn_kernel<<<8192, 256, smAttn>>>(x, mask, n1g, n1b, qkv_b, proj_b, n2g, n2b);
    fc1_kernel<<<MTILES, 256, smFc1>>>(fc1_b);
    fc2_kernel<<<MTILES, 256, smFc2>>>(fc2_b, out);
}

// round 6
// speedup vs baseline: 3.9273x; 1.0345x over previous
#include <cuda_runtime.h>
#include <cuda_bf16.h>
#include <stdint.h>
#include <math.h>

#define Hh 224
#define Ww 224
#define NT 49
#define SCALE_Q 0.17677669529663687f
#define LN_EPS 1e-5f
#define NTOKENS (8*224*224)          // 401408

// fp32/bf16 activation scratch
__device__ float         g_x1[(size_t)NTOKENS*96];   // x + attn residual (natural)
__device__ __nv_bfloat16 g_x2[(size_t)NTOKENS*96];   // LN2 out (natural)

// pre-swizzled bf16 weights (row stride 104, smem-ready)
__device__ __nv_bfloat16 g_wq[288*104];
__device__ __nv_bfloat16 g_wp[96*104];
__device__ __nv_bfloat16 g_w1[384*104];
__device__ __nv_bfloat16 g_w2[4][96*104];            // fc2 K-chunks

// =====================================================================
// helpers
// =====================================================================
__device__ __forceinline__ uint32_t smem_u32(const void* p) {
    uint32_t a;
    asm("{ .reg .u64 t; cvta.to.shared.u64 t, %1; cvt.u32.u64 %0, t; }" : "=r"(a) : "l"(p));
    return a;
}
__device__ __forceinline__ void ldsm4(uint32_t& r0, uint32_t& r1, uint32_t& r2, uint32_t& r3, uint32_t addr) {
    asm volatile("ldmatrix.sync.aligned.m8n8.x4.shared.b16 {%0,%1,%2,%3}, [%4];"
        : "=r"(r0), "=r"(r1), "=r"(r2), "=r"(r3) : "r"(addr));
}
__device__ __forceinline__ void ldsm4t(uint32_t& r0, uint32_t& r1, uint32_t& r2, uint32_t& r3, uint32_t addr) {
    asm volatile("ldmatrix.sync.aligned.m8n8.x4.trans.shared.b16 {%0,%1,%2,%3}, [%4];"
        : "=r"(r0), "=r"(r1), "=r"(r2), "=r"(r3) : "r"(addr));
}
__device__ __forceinline__ void mma16816(float* c, uint32_t a0, uint32_t a1, uint32_t a2, uint32_t a3,
                                         uint32_t b0, uint32_t b1) {
    asm volatile("mma.sync.aligned.m16n8k16.row.col.f32.bf16.bf16.f32 "
        "{%0,%1,%2,%3},{%4,%5,%6,%7},{%8,%9},{%0,%1,%2,%3};"
        : "+f"(c[0]), "+f"(c[1]), "+f"(c[2]), "+f"(c[3])
        : "r"(a0), "r"(a1), "r"(a2), "r"(a3), "r"(b0), "r"(b1));
}
__device__ __forceinline__ uint32_t packbf2(float a, float b) {
    __nv_bfloat162 p = __floats2bfloat162_rn(a, b);
    return *(uint32_t*)&p;
}
// warp GEMM: 16 rows x 48 cols, K=96. SAE/SBE element strides.
template <int SAE, int SBE>
__device__ __forceinline__ void wgemm_16x48(float c[6][4], uint32_t a_base, uint32_t b_base,
                                            int lane, int row0, int ncol0) {
    const int SA = SAE * 2, SB = SBE * 2;
    uint32_t a_addr = a_base + (uint32_t)(row0 + (lane & 7) + ((lane >> 3) & 1) * 8) * SA + (lane >> 4) * 16;
    uint32_t b_addr = b_base + (uint32_t)(ncol0 + (lane & 7) + (lane >> 4) * 8) * SB + ((lane >> 3) & 1) * 16;
    #pragma unroll
    for (int ks = 0; ks < 6; ks++) {
        uint32_t a0, a1, a2, a3;
        ldsm4(a0, a1, a2, a3, a_addr + ks * 32);
        #pragma unroll
        for (int j = 0; j < 3; j++) {
            uint32_t b0, b1, b2, b3;
            ldsm4(b0, b1, b2, b3, b_addr + (uint32_t)j * 16 * SB + ks * 32);
            mma16816(c[2 * j],     a0, a1, a2, a3, b0, b1);
            mma16816(c[2 * j + 1], a0, a1, a2, a3, b2, b3);
        }
    }
}

// =====================================================================
// weight pre-swizzle
// =====================================================================
__global__ __launch_bounds__(256) void prep_weights(
    const float* __restrict__ qkv_w, const float* __restrict__ proj_w,
    const float* __restrict__ fc1_w, const float* __restrict__ fc2_w)
{
    int i = blockIdx.x * 256 + threadIdx.x;
    if (i >= 1152 * 96) return;
    int row = i / 96, col = i % 96;
    float v; __nv_bfloat16* dst;
    if (row < 288)      { v = qkv_w[row * 96 + col];               dst = g_wq + row * 104 + col; }
    else if (row < 384) { int r = row - 288; v = proj_w[r * 96 + col]; dst = g_wp + r * 104 + col; }
    else if (row < 768) { int r = row - 384; v = fc1_w[r * 96 + col];  dst = g_w1 + r * 104 + col; }
    else { int r = row - 768; int kc = r / 96, n = r % 96;
           v = fc2_w[n * 384 + kc * 96 + col]; dst = g_w2[kc] + n * 104 + col; }
    *dst = __float2bfloat16(v);
}

// =====================================================================
// ATTN: 1 window / block, 256 threads, 3 CTAs/SM  (unchanged from R5)
// =====================================================================
__global__ __launch_bounds__(256, 3) void attn_kernel(
    const float* __restrict__ x, const float* __restrict__ mask,
    const float* __restrict__ n1g, const float* __restrict__ n1b,
    const float* __restrict__ qkv_b, const float* __restrict__ proj_b,
    const float* __restrict__ n2g, const float* __restrict__ n2b)
{
    extern __shared__ char smraw[];
    __nv_bfloat16* As = (__nv_bfloat16*)smraw;              // 64*104
    __nv_bfloat16* Qs = (__nv_bfloat16*)(smraw + 13312);    // 64*296
    __nv_bfloat16* Bc = (__nv_bfloat16*)(smraw + 51200);    // 96*104
    const int tid = threadIdx.x, lane = tid & 31, wid = tid >> 5;
    const int blk = blockIdx.x;
    const int bI = blk >> 10, wi = (blk >> 5) & 31, wj = blk & 31;

    // ---------- LN1 + shifted gather ----------
    {
        const float g0 = n1g[lane], g1 = n1g[lane + 32], g2 = n1g[lane + 64];
        const float b0 = n1b[lane], b1 = n1b[lane + 32], b2 = n1b[lane + 64];
        for (int t = wid; t < 64; t += 8) {
            __nv_bfloat16* dst = As + t * 104;
            if (t < NT) {
                int r  = wi * 7 + t / 7;
                int cl = wj * 7 + t % 7;
                int sr = r + 3;  if (sr >= Hh) sr -= Hh;
                int sc = cl + 3; if (sc >= Ww) sc -= Ww;
                const float* xp = x + ((size_t)(bI * Hh + sr) * Ww + sc) * 96;
                float v0 = xp[lane], v1 = xp[lane + 32], v2 = xp[lane + 64];
                float s = v0 + v1 + v2;
                #pragma unroll
                for (int o = 16; o; o >>= 1) s += __shfl_xor_sync(~0u, s, o);
                float mu = s * (1.0f / 96.0f);
                float d0 = v0 - mu, d1 = v1 - mu, d2 = v2 - mu;
                float vs = d0 * d0 + d1 * d1 + d2 * d2;
                #pragma unroll
                for (int o = 16; o; o >>= 1) vs += __shfl_xor_sync(~0u, vs, o);
                float rs = rsqrtf(vs * (1.0f / 96.0f) + LN_EPS);
                dst[lane]      = __float2bfloat16(d0 * rs * g0 + b0);
                dst[lane + 32] = __float2bfloat16(d1 * rs * g1 + b1);
                dst[lane + 64] = __float2bfloat16(d2 * rs * g2 + b2);
            } else {
                __nv_bfloat16 z = __float2bfloat16(0.f);
                dst[lane] = z; dst[lane + 32] = z; dst[lane + 64] = z;
            }
        }
    }
    __syncthreads();

    const uint32_t a_base = smem_u32(As), q_base = smem_u32(Qs), b_base = smem_u32(Bc);
    const int rt4 = wid >> 1, ch48 = (wid & 1) * 48;

    // ---------- qkv: 3 chunks of 96 cols -> Qs ----------
    for (int ch = 0; ch < 3; ch++) {
        if (ch) __syncthreads();
        {
            const uint4* src = (const uint4*)(g_wq + ch * 96 * 104);
            uint4* dst = (uint4*)Bc;
            for (int i = tid; i < 1248; i += 256) dst[i] = src[i];
        }
        __syncthreads();
        float c[6][4];
        #pragma unroll
        for (int j = 0; j < 6; j++) { c[j][0]=0.f; c[j][1]=0.f; c[j][2]=0.f; c[j][3]=0.f; }
        wgemm_16x48<104, 104>(c, a_base, b_base, lane, rt4 * 16, ch48);
        const float qs = (ch == 0) ? SCALE_Q : 1.0f;
        int row0 = rt4 * 16 + (lane >> 2);
        #pragma unroll
        for (int j = 0; j < 6; j++) {
            int jc = ch * 96 + ch48 + j * 8 + (lane & 3) * 2;
            float bi0 = __ldg(qkv_b + jc), bi1 = __ldg(qkv_b + jc + 1);
            *(uint32_t*)(Qs + row0 * 296 + jc)       = packbf2((c[j][0] + bi0) * qs, (c[j][1] + bi1) * qs);
            *(uint32_t*)(Qs + (row0 + 8) * 296 + jc) = packbf2((c[j][2] + bi0) * qs, (c[j][3] + bi1) * qs);
        }
    }
    __syncthreads();

    // prefetch proj weights into Bc during attention
    {
        const uint4* src = (const uint4*)g_wp;
        uint4* dst = (uint4*)Bc;
        for (int i = tid; i < 1248; i += 256) dst[i] = src[i];
    }

    // ---------- attention: barrier-free, P in registers ----------
    const size_t mb = (size_t)blk * (NT * NT);
    for (int task = wid; task < 12; task += 8) {
        int h = task >> 2, rt = task & 3;
        float c[8][4];
        #pragma unroll
        for (int j = 0; j < 8; j++) { c[j][0]=0.f; c[j][1]=0.f; c[j][2]=0.f; c[j][3]=0.f; }
        uint32_t a_addr = q_base + (uint32_t)(rt * 16 + (lane & 7) + ((lane >> 3) & 1) * 8) * 592 + h * 64 + (lane >> 4) * 16;
        uint32_t b_addr = q_base + (uint32_t)((lane & 7) + (lane >> 4) * 8) * 592 + 192 + h * 64 + ((lane >> 3) & 1) * 16;
        #pragma unroll
        for (int ks = 0; ks < 2; ks++) {
            uint32_t a0, a1, a2, a3;
            ldsm4(a0, a1, a2, a3, a_addr + ks * 32);
            #pragma unroll
            for (int j2 = 0; j2 < 4; j2++) {
                uint32_t b0, b1, b2, b3;
                ldsm4(b0, b1, b2, b3, b_addr + (uint32_t)j2 * 16 * 592 + ks * 32);
                mma16816(c[2 * j2],     a0, a1, a2, a3, b0, b1);
                mma16816(c[2 * j2 + 1], a0, a1, a2, a3, b2, b3);
            }
        }
        int t1 = rt * 16 + (lane >> 2), t2 = t1 + 8;
        bool v1 = t1 < NT, v2 = t2 < NT;
        float mx1 = -1e30f, mx2 = -1e30f;
        #pragma unroll
        for (int j = 0; j < 8; j++) {
            #pragma unroll
            for (int e = 0; e < 2; e++) {
                int u = j * 8 + (lane & 3) * 2 + e;
                float m1 = (v1 && u < NT) ? __ldg(mask + mb + t1 * NT + u) : -1e30f;
                float m2 = (v2 && u < NT) ? __ldg(mask + mb + t2 * NT + u) : -1e30f;
                c[j][e]     += m1; c[j][2 + e] += m2;
                mx1 = fmaxf(mx1, c[j][e]);
                mx2 = fmaxf(mx2, c[j][2 + e]);
            }
        }
        mx1 = fmaxf(mx1, __shfl_xor_sync(~0u, mx1, 1)); mx1 = fmaxf(mx1, __shfl_xor_sync(~0u, mx1, 2));
        mx2 = fmaxf(mx2, __shfl_xor_sync(~0u, mx2, 1)); mx2 = fmaxf(mx2, __shfl_xor_sync(~0u, mx2, 2));
        float s1 = 0.f, s2 = 0.f;
        #pragma unroll
        for (int j = 0; j < 8; j++) {
            c[j][0] = __expf(c[j][0] - mx1); c[j][1] = __expf(c[j][1] - mx1);
            c[j][2] = __expf(c[j][2] - mx2); c[j][3] = __expf(c[j][3] - mx2);
            s1 += c[j][0] + c[j][1]; s2 += c[j][2] + c[j][3];
        }
        s1 += __shfl_xor_sync(~0u, s1, 1); s1 += __shfl_xor_sync(~0u, s1, 2);
        s2 += __shfl_xor_sync(~0u, s2, 1); s2 += __shfl_xor_sync(~0u, s2, 2);
        float i1 = 1.0f / (s1 + 1e-20f), i2 = 1.0f / (s2 + 1e-20f);
        uint32_t ap[4][4];
        #pragma unroll
        for (int s = 0; s < 4; s++) {
            ap[s][0] = packbf2(c[2*s][0]   * i1, c[2*s][1]   * i1);
            ap[s][1] = packbf2(c[2*s][2]   * i2, c[2*s][3]   * i2);
            ap[s][2] = packbf2(c[2*s+1][0] * i1, c[2*s+1][1] * i1);
            ap[s][3] = packbf2(c[2*s+1][2] * i2, c[2*s+1][3] * i2);
        }
        float c2[4][4];
        #pragma unroll
        for (int n = 0; n < 4; n++) { c2[n][0]=0.f; c2[n][1]=0.f; c2[n][2]=0.f; c2[n][3]=0.f; }
        uint32_t vb = q_base + (uint32_t)((lane & 7) + ((lane >> 3) & 1) * 8) * 592 + 384 + h * 64 + (lane >> 4) * 16;
        #pragma unroll
        for (int ks = 0; ks < 4; ks++) {
            uint32_t b0, b1, b2, b3;
            ldsm4t(b0, b1, b2, b3, vb + (uint32_t)ks * 16 * 592);
            mma16816(c2[0], ap[ks][0], ap[ks][1], ap[ks][2], ap[ks][3], b0, b1);
            mma16816(c2[1], ap[ks][0], ap[ks][1], ap[ks][2], ap[ks][3], b2, b3);
            ldsm4t(b0, b1, b2, b3, vb + (uint32_t)ks * 16 * 592 + 32);
            mma16816(c2[2], ap[ks][0], ap[ks][1], ap[ks][2], ap[ks][3], b0, b1);
            mma16816(c2[3], ap[ks][0], ap[ks][1], ap[ks][2], ap[ks][3], b2, b3);
        }
        int row = rt * 16 + (lane >> 2);
        #pragma unroll
        for (int n = 0; n < 4; n++) {
            int col = h * 32 + n * 8 + (lane & 3) * 2;
            *(uint32_t*)(Qs + row * 296 + col)       = packbf2(c2[n][0], c2[n][1]);
            *(uint32_t*)(Qs + (row + 8) * 296 + col) = packbf2(c2[n][2], c2[n][3]);
        }
    }
    __syncthreads();

    // ---------- proj (+bias +residual +fused LN2) ----------
    float c[6][4];
    #pragma unroll
    for (int j = 0; j < 6; j++) { c[j][0]=0.f; c[j][1]=0.f; c[j][2]=0.f; c[j][3]=0.f; }
    wgemm_16x48<296, 104>(c, q_base, b_base, lane, rt4 * 16, ch48);

    int r1 = rt4 * 16 + (lane >> 2), r2 = r1 + 8;
    bool va = r1 < NT, vb2 = r2 < NT;
    size_t nt1 = 0, nt2 = 0;
    {
        int tl = va ? r1 : 0;
        int r = wi * 7 + tl / 7, cl = wj * 7 + tl % 7;
        int sr = r + 3;  if (sr >= Hh) sr -= Hh;
        int sc = cl + 3; if (sc >= Ww) sc -= Ww;
        nt1 = ((size_t)(bI * Hh + sr)) * Ww + sc;
        tl = vb2 ? r2 : 0;
        r = wi * 7 + tl / 7; cl = wj * 7 + tl % 7;
        sr = r + 3;  if (sr >= Hh) sr -= Hh;
        sc = cl + 3; if (sc >= Ww) sc -= Ww;
        nt2 = ((size_t)(bI * Hh + sr)) * Ww + sc;
    }
    float s1a = 0.f, s2a = 0.f, s1b = 0.f, s2b = 0.f;
    #pragma unroll
    for (int j = 0; j < 6; j++) {
        int col = ch48 + j * 8 + (lane & 3) * 2;
        float bi0 = __ldg(proj_b + col), bi1 = __ldg(proj_b + col + 1);
        float2 xa = va  ? *(const float2*)(x + nt1 * 96 + col) : make_float2(0.f, 0.f);
        float2 xb = vb2 ? *(const float2*)(x + nt2 * 96 + col) : make_float2(0.f, 0.f);
        float o0 = c[j][0] + bi0 + xa.x, o1 = c[j][1] + bi1 + xa.y;
        float o2 = c[j][2] + bi0 + xb.x, o3 = c[j][3] + bi1 + xb.y;
        c[j][0] = o0; c[j][1] = o1; c[j][2] = o2; c[j][3] = o3;
        if (va)  *(float2*)(g_x1 + nt1 * 96 + col) = make_float2(o0, o1);
        if (vb2) *(float2*)(g_x1 + nt2 * 96 + col) = make_float2(o2, o3);
        s1a += o0 + o1; s2a += o0 * o0 + o1 * o1;
        s1b += o2 + o3; s2b += o2 * o2 + o3 * o3;
    }
    s1a += __shfl_xor_sync(~0u, s1a, 1); s1a += __shfl_xor_sync(~0u, s1a, 2);
    s2a += __shfl_xor_sync(~0u, s2a, 1); s2a += __shfl_xor_sync(~0u, s2a, 2);
    s1b += __shfl_xor_sync(~0u, s1b, 1); s1b += __shfl_xor_sync(~0u, s1b, 2);
    s2b += __shfl_xor_sync(~0u, s2b, 1); s2b += __shfl_xor_sync(~0u, s2b, 2);
    float* red = (float*)As;
    if ((lane & 3) == 0) {
        red[r1 * 2 + (wid & 1)]       = s1a; red[128 + r1 * 2 + (wid & 1)] = s2a;
        red[r2 * 2 + (wid & 1)]       = s1b; red[128 + r2 * 2 + (wid & 1)] = s2b;
    }
    __syncthreads();
    float mu1 = (red[r1 * 2] + red[r1 * 2 + 1]) * (1.f / 96.f);
    float mu2 = (red[r2 * 2] + red[r2 * 2 + 1]) * (1.f / 96.f);
    float rs1 = rsqrtf((red[128 + r1 * 2] + red[128 + r1 * 2 + 1]) * (1.f / 96.f) - mu1 * mu1 + LN_EPS);
    float rs2 = rsqrtf((red[128 + r2 * 2] + red[128 + r2 * 2 + 1]) * (1.f / 96.f) - mu2 * mu2 + LN_EPS);
    #pragma unroll
    for (int j = 0; j < 6; j++) {
        int col = ch48 + j * 8 + (lane & 3) * 2;
        float gg0 = __ldg(n2g + col), gg1 = __ldg(n2g + col + 1);
        float nb0 = __ldg(n2b + col), nb1 = __ldg(n2b + col + 1);
        if (va)
            *(uint32_t*)(g_x2 + nt1 * 96 + col) =
                packbf2((c[j][0] - mu1) * rs1 * gg0 + nb0, (c[j][1] - mu1) * rs1 * gg1 + nb1);
        if (vb2)
            *(uint32_t*)(g_x2 + nt2 * 96 + col) =
                packbf2((c[j][2] - mu2) * rs2 * gg0 + nb0, (c[j][3] - mu2) * rs2 * gg1 + nb1);
    }
}

// =====================================================================
// MLP merged: 64-row tile, H in smem, double-buffered weight chunks
// smem: As 64x104 (13312) | Hs 64x392 (50176) | Bc[2] 96x104 (2x19968)
// total 103424 -> 2 CTAs/SM
// =====================================================================
__global__ __launch_bounds__(256, 2) void mlp_kernel(
    const float* __restrict__ fc1_b, const float* __restrict__ fc2_b,
    float* __restrict__ out)
{
    extern __shared__ char smraw[];
    __nv_bfloat16* As = (__nv_bfloat16*)smraw;               // 64*104
    __nv_bfloat16* Hs = (__nv_bfloat16*)(smraw + 13312);     // 64*392
    __nv_bfloat16* Bc0 = (__nv_bfloat16*)(smraw + 63488);    // 96*104
    __nv_bfloat16* Bc1 = (__nv_bfloat16*)(smraw + 83456);    // 96*104
    const int tid = threadIdx.x, lane = tid & 31, wid = tid >> 5;
    const int rt4 = wid >> 1, ch48 = (wid & 1) * 48;
    const uint32_t a_base = smem_u32(As), h_base = smem_u32(Hs);
    uint32_t bbase[2] = { smem_u32(Bc0), smem_u32(Bc1) };
    uint4* bdst[2] = { (uint4*)Bc0, (uint4*)Bc1 };

    // stage A tile + fc1 chunk0
    {
        const __nv_bfloat16* a0 = g_x2 + (size_t)blockIdx.x * 64 * 96;
        for (int i = tid; i < 64 * 12; i += 256) {
            int r = i / 12, c8 = i % 12;
            *(uint4*)(As + r * 104 + c8 * 8) = *(const uint4*)(a0 + (size_t)r * 96 + c8 * 8);
        }
        const uint4* src = (const uint4*)g_w1;
        for (int i = tid; i < 1248; i += 256) bdst[0][i] = src[i];
    }
    __syncthreads();

    // ---------- fc1 + GELU -> Hs, pipelined weight staging ----------
    for (int ch = 0; ch < 4; ch++) {
        // prefetch next chunk (fc1 ch+1, or fc2 chunk0 after last) into idle buffer
        {
            const uint4* src = (ch < 3) ? (const uint4*)(g_w1 + (ch + 1) * 96 * 104)
                                        : (const uint4*)(g_w2[0]);
            uint4* d = bdst[(ch + 1) & 1];
            for (int i = tid; i < 1248; i += 256) d[i] = src[i];
        }
        float c[6][4];
        #pragma unroll
        for (int j = 0; j < 6; j++) { c[j][0]=0.f; c[j][1]=0.f; c[j][2]=0.f; c[j][3]=0.f; }
        wgemm_16x48<104, 104>(c, a_base, bbase[ch & 1], lane, rt4 * 16, ch48);
        int row0 = rt4 * 16 + (lane >> 2);
        #pragma unroll
        for (int j = 0; j < 6; j++) {
            int col = ch * 96 + ch48 + j * 8 + (lane & 3) * 2;
            float bi0 = __ldg(fc1_b + col), bi1 = __ldg(fc1_b + col + 1);
            float v0 = c[j][0] + bi0, v1 = c[j][1] + bi1;
            float v2 = c[j][2] + bi0, v3 = c[j][3] + bi1;
            v0 = 0.5f * v0 * (1.0f + erff(v0 * 0.70710678118654752f));
            v1 = 0.5f * v1 * (1.0f + erff(v1 * 0.70710678118654752f));
            v2 = 0.5f * v2 * (1.0f + erff(v2 * 0.70710678118654752f));
            v3 = 0.5f * v3 * (1.0f + erff(v3 * 0.70710678118654752f));
            *(uint32_t*)(Hs + row0 * 392 + col)       = packbf2(v0, v1);
            *(uint32_t*)(Hs + (row0 + 8) * 392 + col) = packbf2(v2, v3);
        }
        __syncthreads();
    }

    // ---------- fc2: accumulate over 4 K-chunks from Hs ----------
    float c2[6][4];
    #pragma unroll
    for (int j = 0; j < 6; j++) { c2[j][0]=0.f; c2[j][1]=0.f; c2[j][2]=0.f; c2[j][3]=0.f; }
    for (int kc = 0; kc < 4; kc++) {
        if (kc < 3) {
            const uint4* src = (const uint4*)(g_w2[kc + 1]);
            uint4* d = bdst[(kc + 1) & 1];
            for (int i = tid; i < 1248; i += 256) d[i] = src[i];
        }
        wgemm_16x48<392, 104>(c2, h_base + kc * 192, bbase[kc & 1], lane, rt4 * 16, ch48);
        __syncthreads();
    }

    // ---------- bias + residual -> out ----------
    const size_t row0 = (size_t)blockIdx.x * 64 + rt4 * 16 + (lane >> 2);
    #pragma unroll
    for (int j = 0; j < 6; j++) {
        int col = ch48 + j * 8 + (lane & 3) * 2;
        float bi0 = __ldg(fc2_b + col), bi1 = __ldg(fc2_b + col + 1);
        float2 r0 = *(const float2*)(g_x1 + row0 * 96 + col);
        float2 r1 = *(const float2*)(g_x1 + (row0 + 8) * 96 + col);
        *(float2*)(out + row0 * 96 + col)       = make_float2(c2[j][0] + bi0 + r0.x, c2[j][1] + bi1 + r0.y);
        *(float2*)(out + (row0 + 8) * 96 + col) = make_float2(c2[j][2] + bi0 + r1.x, c2[j][3] + bi1 + r1.y);
    }
}

// =====================================================================
extern "C" void kernel_launch(void* const* d_in, const int* in_sizes, int n_in,
                              void* d_out, int out_size)
{
    (void)in_sizes; (void)n_in; (void)out_size;
    const float* x      = (const float*)d_in[0];
    const float* mask   = (const float*)d_in[1];
    const float* n1g    = (const float*)d_in[2];
    const float* n1b    = (const float*)d_in[3];
    const float* qkv_w  = (const float*)d_in[4];
    const float* qkv_b  = (const float*)d_in[5];
    const float* proj_w = (const float*)d_in[6];
    const float* proj_b = (const float*)d_in[7];
    const float* n2g    = (const float*)d_in[8];
    const float* n2b    = (const float*)d_in[9];
    const float* fc1_w  = (const float*)d_in[10];
    const float* fc1_b  = (const float*)d_in[11];
    const float* fc2_w  = (const float*)d_in[12];
    const float* fc2_b  = (const float*)d_in[13];
    float* out = (float*)d_out;

    const int smAttn = 71168;
    const int smMlp  = 103424;

    cudaFuncSetAttribute(attn_kernel, cudaFuncAttributeMaxDynamicSharedMemorySize, smAttn);
    cudaFuncSetAttribute(mlp_kernel,  cudaFuncAttributeMaxDynamicSharedMemorySize, smMlp);

    prep_weights<<<432, 256>>>(qkv_w, proj_w, fc1_w, fc2_w);
    attn_kernel<<<8192, 256, smAttn>>>(x, mask, n1g, n1b, qkv_b, proj_b, n2g, n2b);
    mlp_kernel<<<NTOKENS/64, 256, smMlp>>>(fc1_b, fc2_b, out);
}

// round 7
// speedup vs baseline: 4.0649x; 1.0350x over previous
#include <cuda_runtime.h>
#include <cuda_bf16.h>
#include <stdint.h>
#include <math.h>

#define Hh 224
#define Ww 224
#define NT 49
#define SCALE_Q 0.17677669529663687f
#define LN_EPS 1e-5f
#define NTOKENS (8*224*224)          // 401408

// fp32/bf16 activation scratch
__device__ float         g_x1[(size_t)NTOKENS*96];   // x + attn residual (natural)
__device__ __nv_bfloat16 g_x2[(size_t)NTOKENS*96];   // LN2 out (natural)

// pre-swizzled bf16 weights (row stride 104, smem-ready)
__device__ __nv_bfloat16 g_wq[288*104];
__device__ __nv_bfloat16 g_wp[96*104];
__device__ __nv_bfloat16 g_w1[384*104];
__device__ __nv_bfloat16 g_w2[4][96*104];            // fc2 K-chunks

// =====================================================================
// helpers
// =====================================================================
__device__ __forceinline__ uint32_t smem_u32(const void* p) {
    uint32_t a;
    asm("{ .reg .u64 t; cvta.to.shared.u64 t, %1; cvt.u32.u64 %0, t; }" : "=r"(a) : "l"(p));
    return a;
}
__device__ __forceinline__ void ldsm4(uint32_t& r0, uint32_t& r1, uint32_t& r2, uint32_t& r3, uint32_t addr) {
    asm volatile("ldmatrix.sync.aligned.m8n8.x4.shared.b16 {%0,%1,%2,%3}, [%4];"
        : "=r"(r0), "=r"(r1), "=r"(r2), "=r"(r3) : "r"(addr));
}
__device__ __forceinline__ void ldsm4t(uint32_t& r0, uint32_t& r1, uint32_t& r2, uint32_t& r3, uint32_t addr) {
    asm volatile("ldmatrix.sync.aligned.m8n8.x4.trans.shared.b16 {%0,%1,%2,%3}, [%4];"
        : "=r"(r0), "=r"(r1), "=r"(r2), "=r"(r3) : "r"(addr));
}
__device__ __forceinline__ void mma16816(float* c, uint32_t a0, uint32_t a1, uint32_t a2, uint32_t a3,
                                         uint32_t b0, uint32_t b1) {
    asm volatile("mma.sync.aligned.m16n8k16.row.col.f32.bf16.bf16.f32 "
        "{%0,%1,%2,%3},{%4,%5,%6,%7},{%8,%9},{%0,%1,%2,%3};"
        : "+f"(c[0]), "+f"(c[1]), "+f"(c[2]), "+f"(c[3])
        : "r"(a0), "r"(a1), "r"(a2), "r"(a3), "r"(b0), "r"(b1));
}
__device__ __forceinline__ uint32_t packbf2(float a, float b) {
    __nv_bfloat162 p = __floats2bfloat162_rn(a, b);
    return *(uint32_t*)&p;
}
// warp GEMM: 16 rows x 48 cols, K=96. SAE/SBE element strides.
template <int SAE, int SBE>
__device__ __forceinline__ void wgemm_16x48(float c[6][4], uint32_t a_base, uint32_t b_base,
                                            int lane, int row0, int ncol0) {
    const int SA = SAE * 2, SB = SBE * 2;
    uint32_t a_addr = a_base + (uint32_t)(row0 + (lane & 7) + ((lane >> 3) & 1) * 8) * SA + (lane >> 4) * 16;
    uint32_t b_addr = b_base + (uint32_t)(ncol0 + (lane & 7) + (lane >> 4) * 8) * SB + ((lane >> 3) & 1) * 16;
    #pragma unroll
    for (int ks = 0; ks < 6; ks++) {
        uint32_t a0, a1, a2, a3;
        ldsm4(a0, a1, a2, a3, a_addr + ks * 32);
        #pragma unroll
        for (int j = 0; j < 3; j++) {
            uint32_t b0, b1, b2, b3;
            ldsm4(b0, b1, b2, b3, b_addr + (uint32_t)j * 16 * SB + ks * 32);
            mma16816(c[2 * j],     a0, a1, a2, a3, b0, b1);
            mma16816(c[2 * j + 1], a0, a1, a2, a3, b2, b3);
        }
    }
}

// =====================================================================
// weight pre-swizzle
// =====================================================================
__global__ __launch_bounds__(256) void prep_weights(
    const float* __restrict__ qkv_w, const float* __restrict__ proj_w,
    const float* __restrict__ fc1_w, const float* __restrict__ fc2_w)
{
    int i = blockIdx.x * 256 + threadIdx.x;
    if (i >= 1152 * 96) return;
    int row = i / 96, col = i % 96;
    float v; __nv_bfloat16* dst;
    if (row < 288)      { v = qkv_w[row * 96 + col];               dst = g_wq + row * 104 + col; }
    else if (row < 384) { int r = row - 288; v = proj_w[r * 96 + col]; dst = g_wp + r * 104 + col; }
    else if (row < 768) { int r = row - 384; v = fc1_w[r * 96 + col];  dst = g_w1 + r * 104 + col; }
    else { int r = row - 768; int kc = r / 96, n = r % 96;
           v = fc2_w[n * 384 + kc * 96 + col]; dst = g_w2[kc] + n * 104 + col; }
    *dst = __float2bfloat16(v);
}

// =====================================================================
// ATTN: 1 window / block, 256 threads, 3 CTAs/SM
// mask computed in-kernel from Swin region structure (no mask gmem reads)
// =====================================================================
__global__ __launch_bounds__(256, 3) void attn_kernel(
    const float* __restrict__ x,
    const float* __restrict__ n1g, const float* __restrict__ n1b,
    const float* __restrict__ qkv_b, const float* __restrict__ proj_b,
    const float* __restrict__ n2g, const float* __restrict__ n2b)
{
    extern __shared__ char smraw[];
    __nv_bfloat16* As = (__nv_bfloat16*)smraw;              // 64*104
    __nv_bfloat16* Qs = (__nv_bfloat16*)(smraw + 13312);    // 64*296
    __nv_bfloat16* Bc = (__nv_bfloat16*)(smraw + 51200);    // 96*104
    unsigned char* sregs = (unsigned char*)(smraw + 71168); // 64 region bytes
    const int tid = threadIdx.x, lane = tid & 31, wid = tid >> 5;
    const int blk = blockIdx.x;
    const int bI = blk >> 10, wi = (blk >> 5) & 31, wj = blk & 31;

    // ---------- LN1 + shifted gather + region bytes (2-token batches) ----------
    {
        const float g0 = n1g[lane], g1 = n1g[lane + 32], g2 = n1g[lane + 64];
        const float b0 = n1b[lane], b1 = n1b[lane + 32], b2 = n1b[lane + 64];
        for (int t0 = wid; t0 < 64; t0 += 16) {
            int tt[2] = { t0, t0 + 8 };
            float va_[2][3];
            bool vv[2];
            #pragma unroll
            for (int q = 0; q < 2; q++) {
                int t = tt[q];
                vv[q] = (t < NT);
                if (vv[q]) {
                    int r  = wi * 7 + t / 7;
                    int cl = wj * 7 + t % 7;
                    // region byte from pre-roll window coords (matches reference mask)
                    int rr = (r < 217) ? 0 : ((r < 221) ? 1 : 2);
                    int rc = (cl < 217) ? 0 : ((cl < 221) ? 1 : 2);
                    if (lane == 0) sregs[t] = (unsigned char)(rr * 3 + rc);
                    int sr = r + 3;  if (sr >= Hh) sr -= Hh;
                    int sc = cl + 3; if (sc >= Ww) sc -= Ww;
                    const float* xp = x + ((size_t)(bI * Hh + sr) * Ww + sc) * 96;
                    va_[q][0] = xp[lane]; va_[q][1] = xp[lane + 32]; va_[q][2] = xp[lane + 64];
                } else {
                    if (lane == 0) sregs[t] = 15;   // padding: distinct region
                }
            }
            #pragma unroll
            for (int q = 0; q < 2; q++) {
                int t = tt[q];
                __nv_bfloat16* dst = As + t * 104;
                if (vv[q]) {
                    float v0 = va_[q][0], v1 = va_[q][1], v2 = va_[q][2];
                    float s = v0 + v1 + v2;
                    #pragma unroll
                    for (int o = 16; o; o >>= 1) s += __shfl_xor_sync(~0u, s, o);
                    float mu = s * (1.0f / 96.0f);
                    float d0 = v0 - mu, d1 = v1 - mu, d2 = v2 - mu;
                    float vs = d0 * d0 + d1 * d1 + d2 * d2;
                    #pragma unroll
                    for (int o = 16; o; o >>= 1) vs += __shfl_xor_sync(~0u, vs, o);
                    float rs = rsqrtf(vs * (1.0f / 96.0f) + LN_EPS);
                    dst[lane]      = __float2bfloat16(d0 * rs * g0 + b0);
                    dst[lane + 32] = __float2bfloat16(d1 * rs * g1 + b1);
                    dst[lane + 64] = __float2bfloat16(d2 * rs * g2 + b2);
                } else {
                    __nv_bfloat16 z = __float2bfloat16(0.f);
                    dst[lane] = z; dst[lane + 32] = z; dst[lane + 64] = z;
                }
            }
        }
    }
    __syncthreads();

    const uint32_t a_base = smem_u32(As), q_base = smem_u32(Qs), b_base = smem_u32(Bc);
    const int rt4 = wid >> 1, ch48 = (wid & 1) * 48;

    // ---------- qkv: 3 chunks of 96 cols -> Qs ----------
    for (int ch = 0; ch < 3; ch++) {
        if (ch) __syncthreads();
        {
            const uint4* src = (const uint4*)(g_wq + ch * 96 * 104);
            uint4* dst = (uint4*)Bc;
            for (int i = tid; i < 1248; i += 256) dst[i] = src[i];
        }
        __syncthreads();
        float c[6][4];
        #pragma unroll
        for (int j = 0; j < 6; j++) { c[j][0]=0.f; c[j][1]=0.f; c[j][2]=0.f; c[j][3]=0.f; }
        wgemm_16x48<104, 104>(c, a_base, b_base, lane, rt4 * 16, ch48);
        const float qs = (ch == 0) ? SCALE_Q : 1.0f;
        int row0 = rt4 * 16 + (lane >> 2);
        #pragma unroll
        for (int j = 0; j < 6; j++) {
            int jc = ch * 96 + ch48 + j * 8 + (lane & 3) * 2;
            float bi0 = __ldg(qkv_b + jc), bi1 = __ldg(qkv_b + jc + 1);
            *(uint32_t*)(Qs + row0 * 296 + jc)       = packbf2((c[j][0] + bi0) * qs, (c[j][1] + bi1) * qs);
            *(uint32_t*)(Qs + (row0 + 8) * 296 + jc) = packbf2((c[j][2] + bi0) * qs, (c[j][3] + bi1) * qs);
        }
    }
    __syncthreads();

    // prefetch proj weights into Bc during attention
    {
        const uint4* src = (const uint4*)g_wp;
        uint4* dst = (uint4*)Bc;
        for (int i = tid; i < 1248; i += 256) dst[i] = src[i];
    }

    // ---------- attention: barrier-free, P in registers, mask from regions ----------
    for (int task = wid; task < 12; task += 8) {
        int h = task >> 2, rt = task & 3;
        float c[8][4];
        #pragma unroll
        for (int j = 0; j < 8; j++) { c[j][0]=0.f; c[j][1]=0.f; c[j][2]=0.f; c[j][3]=0.f; }
        uint32_t a_addr = q_base + (uint32_t)(rt * 16 + (lane & 7) + ((lane >> 3) & 1) * 8) * 592 + h * 64 + (lane >> 4) * 16;
        uint32_t b_addr = q_base + (uint32_t)((lane & 7) + (lane >> 4) * 8) * 592 + 192 + h * 64 + ((lane >> 3) & 1) * 16;
        #pragma unroll
        for (int ks = 0; ks < 2; ks++) {
            uint32_t a0, a1, a2, a3;
            ldsm4(a0, a1, a2, a3, a_addr + ks * 32);
            #pragma unroll
            for (int j2 = 0; j2 < 4; j2++) {
                uint32_t b0, b1, b2, b3;
                ldsm4(b0, b1, b2, b3, b_addr + (uint32_t)j2 * 16 * 592 + ks * 32);
                mma16816(c[2 * j2],     a0, a1, a2, a3, b0, b1);
                mma16816(c[2 * j2 + 1], a0, a1, a2, a3, b2, b3);
            }
        }
        int t1 = rt * 16 + (lane >> 2), t2 = t1 + 8;
        int reg1 = sregs[t1], reg2 = sregs[t2];
        float mx1 = -1e30f, mx2 = -1e30f;
        #pragma unroll
        for (int j = 0; j < 8; j++) {
            #pragma unroll
            for (int e = 0; e < 2; e++) {
                int u = j * 8 + (lane & 3) * 2 + e;
                int ru = sregs[u];
                c[j][e]     += (ru == reg1) ? 0.f : -100.f;
                c[j][2 + e] += (ru == reg2) ? 0.f : -100.f;
                mx1 = fmaxf(mx1, c[j][e]);
                mx2 = fmaxf(mx2, c[j][2 + e]);
            }
        }
        mx1 = fmaxf(mx1, __shfl_xor_sync(~0u, mx1, 1)); mx1 = fmaxf(mx1, __shfl_xor_sync(~0u, mx1, 2));
        mx2 = fmaxf(mx2, __shfl_xor_sync(~0u, mx2, 1)); mx2 = fmaxf(mx2, __shfl_xor_sync(~0u, mx2, 2));
        float s1 = 0.f, s2 = 0.f;
        #pragma unroll
        for (int j = 0; j < 8; j++) {
            c[j][0] = __expf(c[j][0] - mx1); c[j][1] = __expf(c[j][1] - mx1);
            c[j][2] = __expf(c[j][2] - mx2); c[j][3] = __expf(c[j][3] - mx2);
            s1 += c[j][0] + c[j][1]; s2 += c[j][2] + c[j][3];
        }
        s1 += __shfl_xor_sync(~0u, s1, 1); s1 += __shfl_xor_sync(~0u, s1, 2);
        s2 += __shfl_xor_sync(~0u, s2, 1); s2 += __shfl_xor_sync(~0u, s2, 2);
        float i1 = 1.0f / (s1 + 1e-20f), i2 = 1.0f / (s2 + 1e-20f);
        uint32_t ap[4][4];
        #pragma unroll
        for (int s = 0; s < 4; s++) {
            ap[s][0] = packbf2(c[2*s][0]   * i1, c[2*s][1]   * i1);
            ap[s][1] = packbf2(c[2*s][2]   * i2, c[2*s][3]   * i2);
            ap[s][2] = packbf2(c[2*s+1][0] * i1, c[2*s+1][1] * i1);
            ap[s][3] = packbf2(c[2*s+1][2] * i2, c[2*s+1][3] * i2);
        }
        float c2[4][4];
        #pragma unroll
        for (int n = 0; n < 4; n++) { c2[n][0]=0.f; c2[n][1]=0.f; c2[n][2]=0.f; c2[n][3]=0.f; }
        uint32_t vb = q_base + (uint32_t)((lane & 7) + ((lane >> 3) & 1) * 8) * 592 + 384 + h * 64 + (lane >> 4) * 16;
        #pragma unroll
        for (int ks = 0; ks < 4; ks++) {
            uint32_t b0, b1, b2, b3;
            ldsm4t(b0, b1, b2, b3, vb + (uint32_t)ks * 16 * 592);
            mma16816(c2[0], ap[ks][0], ap[ks][1], ap[ks][2], ap[ks][3], b0, b1);
            mma16816(c2[1], ap[ks][0], ap[ks][1], ap[ks][2], ap[ks][3], b2, b3);
            ldsm4t(b0, b1, b2, b3, vb + (uint32_t)ks * 16 * 592 + 32);
            mma16816(c2[2], ap[ks][0], ap[ks][1], ap[ks][2], ap[ks][3], b0, b1);
            mma16816(c2[3], ap[ks][0], ap[ks][1], ap[ks][2], ap[ks][3], b2, b3);
        }
        int row = rt * 16 + (lane >> 2);
        #pragma unroll
        for (int n = 0; n < 4; n++) {
            int col = h * 32 + n * 8 + (lane & 3) * 2;
            *(uint32_t*)(Qs + row * 296 + col)       = packbf2(c2[n][0], c2[n][1]);
            *(uint32_t*)(Qs + (row + 8) * 296 + col) = packbf2(c2[n][2], c2[n][3]);
        }
    }
    __syncthreads();

    // ---------- proj (+bias +residual +fused LN2) ----------
    float c[6][4];
    #pragma unroll
    for (int j = 0; j < 6; j++) { c[j][0]=0.f; c[j][1]=0.f; c[j][2]=0.f; c[j][3]=0.f; }
    wgemm_16x48<296, 104>(c, q_base, b_base, lane, rt4 * 16, ch48);

    int r1 = rt4 * 16 + (lane >> 2), r2 = r1 + 8;
    bool va = r1 < NT, vb2 = r2 < NT;
    size_t nt1 = 0, nt2 = 0;
    {
        int tl = va ? r1 : 0;
        int r = wi * 7 + tl / 7, cl = wj * 7 + tl % 7;
        int sr = r + 3;  if (sr >= Hh) sr -= Hh;
        int sc = cl + 3; if (sc >= Ww) sc -= Ww;
        nt1 = ((size_t)(bI * Hh + sr)) * Ww + sc;
        tl = vb2 ? r2 : 0;
        r = wi * 7 + tl / 7; cl = wj * 7 + tl % 7;
        sr = r + 3;  if (sr >= Hh) sr -= Hh;
        sc = cl + 3; if (sc >= Ww) sc -= Ww;
        nt2 = ((size_t)(bI * Hh + sr)) * Ww + sc;
    }
    float s1a = 0.f, s2a = 0.f, s1b = 0.f, s2b = 0.f;
    #pragma unroll
    for (int j = 0; j < 6; j++) {
        int col = ch48 + j * 8 + (lane & 3) * 2;
        float bi0 = __ldg(proj_b + col), bi1 = __ldg(proj_b + col + 1);
        float2 xa = va  ? *(const float2*)(x + nt1 * 96 + col) : make_float2(0.f, 0.f);
        float2 xb = vb2 ? *(const float2*)(x + nt2 * 96 + col) : make_float2(0.f, 0.f);
        float o0 = c[j][0] + bi0 + xa.x, o1 = c[j][1] + bi1 + xa.y;
        float o2 = c[j][2] + bi0 + xb.x, o3 = c[j][3] + bi1 + xb.y;
        c[j][0] = o0; c[j][1] = o1; c[j][2] = o2; c[j][3] = o3;
        if (va)  *(float2*)(g_x1 + nt1 * 96 + col) = make_float2(o0, o1);
        if (vb2) *(float2*)(g_x1 + nt2 * 96 + col) = make_float2(o2, o3);
        s1a += o0 + o1; s2a += o0 * o0 + o1 * o1;
        s1b += o2 + o3; s2b += o2 * o2 + o3 * o3;
    }
    s1a += __shfl_xor_sync(~0u, s1a, 1); s1a += __shfl_xor_sync(~0u, s1a, 2);
    s2a += __shfl_xor_sync(~0u, s2a, 1); s2a += __shfl_xor_sync(~0u, s2a, 2);
    s1b += __shfl_xor_sync(~0u, s1b, 1); s1b += __shfl_xor_sync(~0u, s1b, 2);
    s2b += __shfl_xor_sync(~0u, s2b, 1); s2b += __shfl_xor_sync(~0u, s2b, 2);
    float* red = (float*)As;
    if ((lane & 3) == 0) {
        red[r1 * 2 + (wid & 1)]       = s1a; red[128 + r1 * 2 + (wid & 1)] = s2a;
        red[r2 * 2 + (wid & 1)]       = s1b; red[128 + r2 * 2 + (wid & 1)] = s2b;
    }
    __syncthreads();
    float mu1 = (red[r1 * 2] + red[r1 * 2 + 1]) * (1.f / 96.f);
    float mu2 = (red[r2 * 2] + red[r2 * 2 + 1]) * (1.f / 96.f);
    float rs1 = rsqrtf((red[128 + r1 * 2] + red[128 + r1 * 2 + 1]) * (1.f / 96.f) - mu1 * mu1 + LN_EPS);
    float rs2 = rsqrtf((red[128 + r2 * 2] + red[128 + r2 * 2 + 1]) * (1.f / 96.f) - mu2 * mu2 + LN_EPS);
    #pragma unroll
    for (int j = 0; j < 6; j++) {
        int col = ch48 + j * 8 + (lane & 3) * 2;
        float gg0 = __ldg(n2g + col), gg1 = __ldg(n2g + col + 1);
        float nb0 = __ldg(n2b + col), nb1 = __ldg(n2b + col + 1);
        if (va)
            *(uint32_t*)(g_x2 + nt1 * 96 + col) =
                packbf2((c[j][0] - mu1) * rs1 * gg0 + nb0, (c[j][1] - mu1) * rs1 * gg1 + nb1);
        if (vb2)
            *(uint32_t*)(g_x2 + nt2 * 96 + col) =
                packbf2((c[j][2] - mu2) * rs2 * gg0 + nb0, (c[j][3] - mu2) * rs2 * gg1 + nb1);
    }
}

// =====================================================================
// MLP merged: 64-row tile, H in smem, double-buffered weight chunks
// =====================================================================
__global__ __launch_bounds__(256, 2) void mlp_kernel(
    const float* __restrict__ fc1_b, const float* __restrict__ fc2_b,
    float* __restrict__ out)
{
    extern __shared__ char smraw[];
    __nv_bfloat16* As = (__nv_bfloat16*)smraw;               // 64*104
    __nv_bfloat16* Hs = (__nv_bfloat16*)(smraw + 13312);     // 64*392
    __nv_bfloat16* Bc0 = (__nv_bfloat16*)(smraw + 63488);    // 96*104
    __nv_bfloat16* Bc1 = (__nv_bfloat16*)(smraw + 83456);    // 96*104
    const int tid = threadIdx.x, lane = tid & 31, wid = tid >> 5;
    const int rt4 = wid >> 1, ch48 = (wid & 1) * 48;
    const uint32_t a_base = smem_u32(As), h_base = smem_u32(Hs);
    uint32_t bbase[2] = { smem_u32(Bc0), smem_u32(Bc1) };
    uint4* bdst[2] = { (uint4*)Bc0, (uint4*)Bc1 };

    {
        const __nv_bfloat16* a0 = g_x2 + (size_t)blockIdx.x * 64 * 96;
        for (int i = tid; i < 64 * 12; i += 256) {
            int r = i / 12, c8 = i % 12;
            *(uint4*)(As + r * 104 + c8 * 8) = *(const uint4*)(a0 + (size_t)r * 96 + c8 * 8);
        }
        const uint4* src = (const uint4*)g_w1;
        for (int i = tid; i < 1248; i += 256) bdst[0][i] = src[i];
    }
    __syncthreads();

    // ---------- fc1 + GELU -> Hs, pipelined weight staging ----------
    for (int ch = 0; ch < 4; ch++) {
        {
            const uint4* src = (ch < 3) ? (const uint4*)(g_w1 + (ch + 1) * 96 * 104)
                                        : (const uint4*)(g_w2[0]);
            uint4* d = bdst[(ch + 1) & 1];
            for (int i = tid; i < 1248; i += 256) d[i] = src[i];
        }
        float c[6][4];
        #pragma unroll
        for (int j = 0; j < 6; j++) { c[j][0]=0.f; c[j][1]=0.f; c[j][2]=0.f; c[j][3]=0.f; }
        wgemm_16x48<104, 104>(c, a_base, bbase[ch & 1], lane, rt4 * 16, ch48);
        int row0 = rt4 * 16 + (lane >> 2);
        #pragma unroll
        for (int j = 0; j < 6; j++) {
            int col = ch * 96 + ch48 + j * 8 + (lane & 3) * 2;
            float bi0 = __ldg(fc1_b + col), bi1 = __ldg(fc1_b + col + 1);
            float v0 = c[j][0] + bi0, v1 = c[j][1] + bi1;
            float v2 = c[j][2] + bi0, v3 = c[j][3] + bi1;
            v0 = 0.5f * v0 * (1.0f + erff(v0 * 0.70710678118654752f));
            v1 = 0.5f * v1 * (1.0f + erff(v1 * 0.70710678118654752f));
            v2 = 0.5f * v2 * (1.0f + erff(v2 * 0.70710678118654752f));
            v3 = 0.5f * v3 * (1.0f + erff(v3 * 0.70710678118654752f));
            *(uint32_t*)(Hs + row0 * 392 + col)       = packbf2(v0, v1);
            *(uint32_t*)(Hs + (row0 + 8) * 392 + col) = packbf2(v2, v3);
        }
        __syncthreads();
    }

    // ---------- fc2: accumulate over 4 K-chunks from Hs ----------
    float c2[6][4];
    #pragma unroll
    for (int j = 0; j < 6; j++) { c2[j][0]=0.f; c2[j][1]=0.f; c2[j][2]=0.f; c2[j][3]=0.f; }
    for (int kc = 0; kc < 4; kc++) {
        if (kc < 3) {
            const uint4* src = (const uint4*)(g_w2[kc + 1]);
            uint4* d = bdst[(kc + 1) & 1];
            for (int i = tid; i < 1248; i += 256) d[i] = src[i];
        }
        wgemm_16x48<392, 104>(c2, h_base + kc * 192, bbase[kc & 1], lane, rt4 * 16, ch48);
        __syncthreads();
    }

    // ---------- bias + residual -> out ----------
    const size_t row0 = (size_t)blockIdx.x * 64 + rt4 * 16 + (lane >> 2);
    #pragma unroll
    for (int j = 0; j < 6; j++) {
        int col = ch48 + j * 8 + (lane & 3) * 2;
        float bi0 = __ldg(fc2_b + col), bi1 = __ldg(fc2_b + col + 1);
        float2 r0 = *(const float2*)(g_x1 + row0 * 96 + col);
        float2 r1 = *(const float2*)(g_x1 + (row0 + 8) * 96 + col);
        *(float2*)(out + row0 * 96 + col)       = make_float2(c2[j][0] + bi0 + r0.x, c2[j][1] + bi1 + r0.y);
        *(float2*)(out + (row0 + 8) * 96 + col) = make_float2(c2[j][2] + bi0 + r1.x, c2[j][3] + bi1 + r1.y);
    }
}

// =====================================================================
extern "C" void kernel_launch(void* const* d_in, const int* in_sizes, int n_in,
                              void* d_out, int out_size)
{
    (void)in_sizes; (void)n_in; (void)out_size;
    const float* x      = (const float*)d_in[0];
    const float* n1g    = (const float*)d_in[2];
    const float* n1b    = (const float*)d_in[3];
    const float* qkv_w  = (const float*)d_in[4];
    const float* qkv_b  = (const float*)d_in[5];
    const float* proj_w = (const float*)d_in[6];
    const float* proj_b = (const float*)d_in[7];
    const float* n2g    = (const float*)d_in[8];
    const float* n2b    = (const float*)d_in[9];
    const float* fc1_w  = (const float*)d_in[10];
    const float* fc1_b  = (const float*)d_in[11];
    const float* fc2_w  = (const float*)d_in[12];
    const float* fc2_b  = (const float*)d_in[13];
    float* out = (float*)d_out;

    const int smAttn = 71296;
    const int smMlp  = 103424;

    cudaFuncSetAttribute(attn_kernel, cudaFuncAttributeMaxDynamicSharedMemorySize, smAttn);
    cudaFuncSetAttribute(mlp_kernel,  cudaFuncAttributeMaxDynamicSharedMemorySize, smMlp);

    prep_weights<<<432, 256>>>(qkv_w, proj_w, fc1_w, fc2_w);
    attn_kernel<<<8192, 256, smAttn>>>(x, n1g, n1b, qkv_b, proj_b, n2g, n2b);
    mlp_kernel<<<NTOKENS/64, 256, smMlp>>>(fc1_b, fc2_b, out);
}

// round 9
// speedup vs baseline: 4.0997x; 1.0086x over previous
#include <cuda_runtime.h>
#include <cuda_bf16.h>
#include <stdint.h>
#include <math.h>

#define Hh 224
#define Ww 224
#define NT 49
#define SCALE_Q 0.17677669529663687f
#define LN_EPS 1e-5f
#define NTOKENS (8*224*224)          // 401408

// fp32/bf16 activation scratch
__device__ float         g_x1[(size_t)NTOKENS*96];   // x + attn residual (natural)
__device__ __nv_bfloat16 g_x2[(size_t)NTOKENS*96];   // LN2 out (natural)

// pre-swizzled bf16 weights (row stride 104, smem-ready)
__device__ __nv_bfloat16 g_wq[288*104];
__device__ __nv_bfloat16 g_wp[96*104];
__device__ __nv_bfloat16 g_w1[384*104];
__device__ __nv_bfloat16 g_w2[4][96*104];            // fc2 K-chunks

// =====================================================================
// helpers
// =====================================================================
__device__ __forceinline__ uint32_t smem_u32(const void* p) {
    uint32_t a;
    asm("{ .reg .u64 t; cvta.to.shared.u64 t, %1; cvt.u32.u64 %0, t; }" : "=r"(a) : "l"(p));
    return a;
}
__device__ __forceinline__ void ldsm4(uint32_t& r0, uint32_t& r1, uint32_t& r2, uint32_t& r3, uint32_t addr) {
    asm volatile("ldmatrix.sync.aligned.m8n8.x4.shared.b16 {%0,%1,%2,%3}, [%4];"
        : "=r"(r0), "=r"(r1), "=r"(r2), "=r"(r3) : "r"(addr));
}
__device__ __forceinline__ void ldsm4t(uint32_t& r0, uint32_t& r1, uint32_t& r2, uint32_t& r3, uint32_t addr) {
    asm volatile("ldmatrix.sync.aligned.m8n8.x4.trans.shared.b16 {%0,%1,%2,%3}, [%4];"
        : "=r"(r0), "=r"(r1), "=r"(r2), "=r"(r3) : "r"(addr));
}
__device__ __forceinline__ void mma16816(float* c, uint32_t a0, uint32_t a1, uint32_t a2, uint32_t a3,
                                         uint32_t b0, uint32_t b1) {
    asm volatile("mma.sync.aligned.m16n8k16.row.col.f32.bf16.bf16.f32 "
        "{%0,%1,%2,%3},{%4,%5,%6,%7},{%8,%9},{%0,%1,%2,%3};"
        : "+f"(c[0]), "+f"(c[1]), "+f"(c[2]), "+f"(c[3])
        : "r"(a0), "r"(a1), "r"(a2), "r"(a3), "r"(b0), "r"(b1));
}
__device__ __forceinline__ uint32_t packbf2(float a, float b) {
    __nv_bfloat162 p = __floats2bfloat162_rn(a, b);
    return *(uint32_t*)&p;
}
// warp GEMM: 16 rows x 32 cols, K=96. SAE/SBE element strides.
template <int SAE, int SBE>
__device__ __forceinline__ void wgemm_16x32(float c[4][4], uint32_t a_base, uint32_t b_base,
                                            int lane, int row0, int ncol0) {
    const int SA = SAE * 2, SB = SBE * 2;
    uint32_t a_addr = a_base + (uint32_t)(row0 + (lane & 7) + ((lane >> 3) & 1) * 8) * SA + (lane >> 4) * 16;
    uint32_t b_addr = b_base + (uint32_t)(ncol0 + (lane & 7) + (lane >> 4) * 8) * SB + ((lane >> 3) & 1) * 16;
    #pragma unroll
    for (int ks = 0; ks < 6; ks++) {
        uint32_t a0, a1, a2, a3;
        ldsm4(a0, a1, a2, a3, a_addr + ks * 32);
        #pragma unroll
        for (int j = 0; j < 2; j++) {
            uint32_t b0, b1, b2, b3;
            ldsm4(b0, b1, b2, b3, b_addr + (uint32_t)j * 16 * SB + ks * 32);
            mma16816(c[2 * j],     a0, a1, a2, a3, b0, b1);
            mma16816(c[2 * j + 1], a0, a1, a2, a3, b2, b3);
        }
    }
}

// =====================================================================
// weight pre-swizzle
// =====================================================================
__global__ __launch_bounds__(256) void prep_weights(
    const float* __restrict__ qkv_w, const float* __restrict__ proj_w,
    const float* __restrict__ fc1_w, const float* __restrict__ fc2_w)
{
    int i = blockIdx.x * 256 + threadIdx.x;
    if (i >= 1152 * 96) return;
    int row = i / 96, col = i % 96;
    float v; __nv_bfloat16* dst;
    if (row < 288)      { v = qkv_w[row * 96 + col];               dst = g_wq + row * 104 + col; }
    else if (row < 384) { int r = row - 288; v = proj_w[r * 96 + col]; dst = g_wp + r * 104 + col; }
    else if (row < 768) { int r = row - 384; v = fc1_w[r * 96 + col];  dst = g_w1 + r * 104 + col; }
    else { int r = row - 768; int kc = r / 96, n = r % 96;
           v = fc2_w[n * 384 + kc * 96 + col]; dst = g_w2[kc] + n * 104 + col; }
    *dst = __float2bfloat16(v);
}

// =====================================================================
// ATTN: 1 window / block, 384 threads (12 warps), 2 CTAs/SM
// warp grid 4 rows x 3 cols; attention = exactly 1 task per warp
// =====================================================================
__global__ __launch_bounds__(384, 2) void attn_kernel(
    const float* __restrict__ x,
    const float* __restrict__ n1g, const float* __restrict__ n1b,
    const float* __restrict__ qkv_b, const float* __restrict__ proj_b,
    const float* __restrict__ n2g, const float* __restrict__ n2b)
{
    extern __shared__ char smraw[];
    __nv_bfloat16* As = (__nv_bfloat16*)smraw;              // 64*104
    __nv_bfloat16* Qs = (__nv_bfloat16*)(smraw + 13312);    // 64*296
    __nv_bfloat16* Bc = (__nv_bfloat16*)(smraw + 51200);    // 96*104
    unsigned char* sregs = (unsigned char*)(smraw + 71168); // 64 region bytes
    const int tid = threadIdx.x, lane = tid & 31, wid = tid >> 5;
    const int blk = blockIdx.x;
    const int bI = blk >> 10, wi = (blk >> 5) & 31, wj = blk & 31;
    const int rt = wid & 3, cw = wid >> 2;                   // 4x3 warp grid

    // ---------- LN1 + shifted gather + region bytes ----------
    {
        const float g0 = n1g[lane], g1 = n1g[lane + 32], g2 = n1g[lane + 64];
        const float b0 = n1b[lane], b1 = n1b[lane + 32], b2 = n1b[lane + 64];
        for (int t0 = wid; t0 < 64; t0 += 24) {
            int tt[2] = { t0, t0 + 12 };
            float va_[2][3];
            bool vv[2];
            #pragma unroll
            for (int q = 0; q < 2; q++) {
                int t = tt[q];
                vv[q] = (t < 64) && (t < NT);
                if (t < 64 && lane == 0) sregs[t] = 15;
                if (vv[q]) {
                    int r  = wi * 7 + t / 7;
                    int cl = wj * 7 + t % 7;
                    int rr = (r < 217) ? 0 : ((r < 221) ? 1 : 2);
                    int rc = (cl < 217) ? 0 : ((cl < 221) ? 1 : 2);
                    if (lane == 0) sregs[t] = (unsigned char)(rr * 3 + rc);
                    int sr = r + 3;  if (sr >= Hh) sr -= Hh;
                    int sc = cl + 3; if (sc >= Ww) sc -= Ww;
                    const float* xp = x + ((size_t)(bI * Hh + sr) * Ww + sc) * 96;
                    va_[q][0] = xp[lane]; va_[q][1] = xp[lane + 32]; va_[q][2] = xp[lane + 64];
                }
            }
            #pragma unroll
            for (int q = 0; q < 2; q++) {
                int t = tt[q];
                if (t >= 64) continue;
                __nv_bfloat16* dst = As + t * 104;
                if (vv[q]) {
                    float v0 = va_[q][0], v1 = va_[q][1], v2 = va_[q][2];
                    float s = v0 + v1 + v2;
                    #pragma unroll
                    for (int o = 16; o; o >>= 1) s += __shfl_xor_sync(~0u, s, o);
                    float mu = s * (1.0f / 96.0f);
                    float d0 = v0 - mu, d1 = v1 - mu, d2 = v2 - mu;
                    float vs = d0 * d0 + d1 * d1 + d2 * d2;
                    #pragma unroll
                    for (int o = 16; o; o >>= 1) vs += __shfl_xor_sync(~0u, vs, o);
                    float rs = rsqrtf(vs * (1.0f / 96.0f) + LN_EPS);
                    dst[lane]      = __float2bfloat16(d0 * rs * g0 + b0);
                    dst[lane + 32] = __float2bfloat16(d1 * rs * g1 + b1);
                    dst[lane + 64] = __float2bfloat16(d2 * rs * g2 + b2);
                } else {
                    __nv_bfloat16 z = __float2bfloat16(0.f);
                    dst[lane] = z; dst[lane + 32] = z; dst[lane + 64] = z;
                }
            }
        }
    }
    __syncthreads();

    const uint32_t a_base = smem_u32(As), q_base = smem_u32(Qs), b_base = smem_u32(Bc);

    // ---------- qkv: 3 chunks of 96 cols -> Qs ----------
    for (int ch = 0; ch < 3; ch++) {
        if (ch) __syncthreads();
        {
            const uint4* src = (const uint4*)(g_wq + ch * 96 * 104);
            uint4* dst = (uint4*)Bc;
            for (int i = tid; i < 1248; i += 384) dst[i] = src[i];
        }
        __syncthreads();
        float c[4][4];
        #pragma unroll
        for (int j = 0; j < 4; j++) { c[j][0]=0.f; c[j][1]=0.f; c[j][2]=0.f; c[j][3]=0.f; }
        wgemm_16x32<104, 104>(c, a_base, b_base, lane, rt * 16, cw * 32);
        const float qs = (ch == 0) ? SCALE_Q : 1.0f;
        int row0 = rt * 16 + (lane >> 2);
        #pragma unroll
        for (int j = 0; j < 4; j++) {
            int jc = ch * 96 + cw * 32 + j * 8 + (lane & 3) * 2;
            float bi0 = __ldg(qkv_b + jc), bi1 = __ldg(qkv_b + jc + 1);
            *(uint32_t*)(Qs + row0 * 296 + jc)       = packbf2((c[j][0] + bi0) * qs, (c[j][1] + bi1) * qs);
            *(uint32_t*)(Qs + (row0 + 8) * 296 + jc) = packbf2((c[j][2] + bi0) * qs, (c[j][3] + bi1) * qs);
        }
    }
    __syncthreads();

    // prefetch proj weights during attention
    {
        const uint4* src = (const uint4*)g_wp;
        uint4* dst = (uint4*)Bc;
        for (int i = tid; i < 1248; i += 384) dst[i] = src[i];
    }

    // ---------- attention: exactly 1 task per warp (h=cw, rowtile=rt) ----------
    {
        const int h = cw;
        float c[8][4];
        #pragma unroll
        for (int j = 0; j < 8; j++) { c[j][0]=0.f; c[j][1]=0.f; c[j][2]=0.f; c[j][3]=0.f; }
        uint32_t a_addr = q_base + (uint32_t)(rt * 16 + (lane & 7) + ((lane >> 3) & 1) * 8) * 592 + h * 64 + (lane >> 4) * 16;
        uint32_t b_addr = q_base + (uint32_t)((lane & 7) + (lane >> 4) * 8) * 592 + 192 + h * 64 + ((lane >> 3) & 1) * 16;
        #pragma unroll
        for (int ks = 0; ks < 2; ks++) {
            uint32_t a0, a1, a2, a3;
            ldsm4(a0, a1, a2, a3, a_addr + ks * 32);
            #pragma unroll
            for (int j2 = 0; j2 < 4; j2++) {
                uint32_t b0, b1, b2, b3;
                ldsm4(b0, b1, b2, b3, b_addr + (uint32_t)j2 * 16 * 592 + ks * 32);
                mma16816(c[2 * j2],     a0, a1, a2, a3, b0, b1);
                mma16816(c[2 * j2 + 1], a0, a1, a2, a3, b2, b3);
            }
        }
        int t1 = rt * 16 + (lane >> 2), t2 = t1 + 8;
        int reg1 = sregs[t1], reg2 = sregs[t2];
        float mx1 = -1e30f, mx2 = -1e30f;
        #pragma unroll
        for (int j = 0; j < 8; j++) {
            #pragma unroll
            for (int e = 0; e < 2; e++) {
                int u = j * 8 + (lane & 3) * 2 + e;
                int ru = sregs[u];
                c[j][e]     += (ru == reg1) ? 0.f : -100.f;
                c[j][2 + e] += (ru == reg2) ? 0.f : -100.f;
                mx1 = fmaxf(mx1, c[j][e]);
                mx2 = fmaxf(mx2, c[j][2 + e]);
            }
        }
        mx1 = fmaxf(mx1, __shfl_xor_sync(~0u, mx1, 1)); mx1 = fmaxf(mx1, __shfl_xor_sync(~0u, mx1, 2));
        mx2 = fmaxf(mx2, __shfl_xor_sync(~0u, mx2, 1)); mx2 = fmaxf(mx2, __shfl_xor_sync(~0u, mx2, 2));
        float s1 = 0.f, s2 = 0.f;
        #pragma unroll
        for (int j = 0; j < 8; j++) {
            c[j][0] = __expf(c[j][0] - mx1); c[j][1] = __expf(c[j][1] - mx1);
            c[j][2] = __expf(c[j][2] - mx2); c[j][3] = __expf(c[j][3] - mx2);
            s1 += c[j][0] + c[j][1]; s2 += c[j][2] + c[j][3];
        }
        s1 += __shfl_xor_sync(~0u, s1, 1); s1 += __shfl_xor_sync(~0u, s1, 2);
        s2 += __shfl_xor_sync(~0u, s2, 1); s2 += __shfl_xor_sync(~0u, s2, 2);
        float i1 = 1.0f / (s1 + 1e-20f), i2 = 1.0f / (s2 + 1e-20f);
        uint32_t ap[4][4];
        #pragma unroll
        for (int s = 0; s < 4; s++) {
            ap[s][0] = packbf2(c[2*s][0]   * i1, c[2*s][1]   * i1);
            ap[s][1] = packbf2(c[2*s][2]   * i2, c[2*s][3]   * i2);
            ap[s][2] = packbf2(c[2*s+1][0] * i1, c[2*s+1][1] * i1);
            ap[s][3] = packbf2(c[2*s+1][2] * i2, c[2*s+1][3] * i2);
        }
        float c2[4][4];
        #pragma unroll
        for (int n = 0; n < 4; n++) { c2[n][0]=0.f; c2[n][1]=0.f; c2[n][2]=0.f; c2[n][3]=0.f; }
        uint32_t vb = q_base + (uint32_t)((lane & 7) + ((lane >> 3) & 1) * 8) * 592 + 384 + h * 64 + (lane >> 4) * 16;
        #pragma unroll
        for (int ks = 0; ks < 4; ks++) {
            uint32_t b0, b1, b2, b3;
            ldsm4t(b0, b1, b2, b3, vb + (uint32_t)ks * 16 * 592);
            mma16816(c2[0], ap[ks][0], ap[ks][1], ap[ks][2], ap[ks][3], b0, b1);
            mma16816(c2[1], ap[ks][0], ap[ks][1], ap[ks][2], ap[ks][3], b2, b3);
            ldsm4t(b0, b1, b2, b3, vb + (uint32_t)ks * 16 * 592 + 32);
            mma16816(c2[2], ap[ks][0], ap[ks][1], ap[ks][2], ap[ks][3], b0, b1);
            mma16816(c2[3], ap[ks][0], ap[ks][1], ap[ks][2], ap[ks][3], b2, b3);
        }
        int row = rt * 16 + (lane >> 2);
        #pragma unroll
        for (int n = 0; n < 4; n++) {
            int col = h * 32 + n * 8 + (lane & 3) * 2;
            *(uint32_t*)(Qs + row * 296 + col)       = packbf2(c2[n][0], c2[n][1]);
            *(uint32_t*)(Qs + (row + 8) * 296 + col) = packbf2(c2[n][2], c2[n][3]);
        }
    }
    __syncthreads();

    // ---------- proj (+bias +residual +fused LN2) ----------
    float c[4][4];
    #pragma unroll
    for (int j = 0; j < 4; j++) { c[j][0]=0.f; c[j][1]=0.f; c[j][2]=0.f; c[j][3]=0.f; }
    wgemm_16x32<296, 104>(c, q_base, b_base, lane, rt * 16, cw * 32);

    int r1 = rt * 16 + (lane >> 2), r2 = r1 + 8;
    bool va = r1 < NT, vb2 = r2 < NT;
    size_t nt1 = 0, nt2 = 0;
    {
        int tl = va ? r1 : 0;
        int r = wi * 7 + tl / 7, cl = wj * 7 + tl % 7;
        int sr = r + 3;  if (sr >= Hh) sr -= Hh;
        int sc = cl + 3; if (sc >= Ww) sc -= Ww;
        nt1 = ((size_t)(bI * Hh + sr)) * Ww + sc;
        tl = vb2 ? r2 : 0;
        r = wi * 7 + tl / 7; cl = wj * 7 + tl % 7;
        sr = r + 3;  if (sr >= Hh) sr -= Hh;
        sc = cl + 3; if (sc >= Ww) sc -= Ww;
        nt2 = ((size_t)(bI * Hh + sr)) * Ww + sc;
    }
    float s1a = 0.f, s2a = 0.f, s1b = 0.f, s2b = 0.f;
    #pragma unroll
    for (int j = 0; j < 4; j++) {
        int col = cw * 32 + j * 8 + (lane & 3) * 2;
        float bi0 = __ldg(proj_b + col), bi1 = __ldg(proj_b + col + 1);
        float2 xa = va  ? *(const float2*)(x + nt1 * 96 + col) : make_float2(0.f, 0.f);
        float2 xb = vb2 ? *(const float2*)(x + nt2 * 96 + col) : make_float2(0.f, 0.f);
        float o0 = c[j][0] + bi0 + xa.x, o1 = c[j][1] + bi1 + xa.y;
        float o2 = c[j][2] + bi0 + xb.x, o3 = c[j][3] + bi1 + xb.y;
        c[j][0] = o0; c[j][1] = o1; c[j][2] = o2; c[j][3] = o3;
        if (va)  *(float2*)(g_x1 + nt1 * 96 + col) = make_float2(o0, o1);
        if (vb2) *(float2*)(g_x1 + nt2 * 96 + col) = make_float2(o2, o3);
        s1a += o0 + o1; s2a += o0 * o0 + o1 * o1;
        s1b += o2 + o3; s2b += o2 * o2 + o3 * o3;
    }
    s1a += __shfl_xor_sync(~0u, s1a, 1); s1a += __shfl_xor_sync(~0u, s1a, 2);
    s2a += __shfl_xor_sync(~0u, s2a, 1); s2a += __shfl_xor_sync(~0u, s2a, 2);
    s1b += __shfl_xor_sync(~0u, s1b, 1); s1b += __shfl_xor_sync(~0u, s1b, 2);
    s2b += __shfl_xor_sync(~0u, s2b, 1); s2b += __shfl_xor_sync(~0u, s2b, 2);
    float* red = (float*)As;     // s1[64][4] at 0, s2[64][4] at 256 — As is dead
    if ((lane & 3) == 0) {
        red[r1 * 4 + cw] = s1a; red[256 + r1 * 4 + cw] = s2a;
        red[r2 * 4 + cw] = s1b; red[256 + r2 * 4 + cw] = s2b;
    }
    __syncthreads();
    float mu1 = (red[r1 * 4] + red[r1 * 4 + 1] + red[r1 * 4 + 2]) * (1.f / 96.f);
    float mu2 = (red[r2 * 4] + red[r2 * 4 + 1] + red[r2 * 4 + 2]) * (1.f / 96.f);
    float rs1 = rsqrtf((red[256 + r1 * 4] + red[256 + r1 * 4 + 1] + red[256 + r1 * 4 + 2]) * (1.f / 96.f) - mu1 * mu1 + LN_EPS);
    float rs2 = rsqrtf((red[256 + r2 * 4] + red[256 + r2 * 4 + 1] + red[256 + r2 * 4 + 2]) * (1.f / 96.f) - mu2 * mu2 + LN_EPS);
    #pragma unroll
    for (int j = 0; j < 4; j++) {
        int col = cw * 32 + j * 8 + (lane & 3) * 2;
        float gg0 = __ldg(n2g + col), gg1 = __ldg(n2g + col + 1);
        float nb0 = __ldg(n2b + col), nb1 = __ldg(n2b + col + 1);
        if (va)
            *(uint32_t*)(g_x2 + nt1 * 96 + col) =
                packbf2((c[j][0] - mu1) * rs1 * gg0 + nb0, (c[j][1] - mu1) * rs1 * gg1 + nb1);
        if (vb2)
            *(uint32_t*)(g_x2 + nt2 * 96 + col) =
                packbf2((c[j][2] - mu2) * rs2 * gg0 + nb0, (c[j][3] - mu2) * rs2 * gg1 + nb1);
    }
}

// =====================================================================
// MLP merged: 64-row tile, 384 threads (4x3 warp grid), H in smem,
// double-buffered weight chunks
// =====================================================================
__global__ __launch_bounds__(384, 2) void mlp_kernel(
    const float* __restrict__ fc1_b, const float* __restrict__ fc2_b,
    float* __restrict__ out)
{
    extern __shared__ char smraw[];
    __nv_bfloat16* As = (__nv_bfloat16*)smraw;               // 64*104
    __nv_bfloat16* Hs = (__nv_bfloat16*)(smraw + 13312);     // 64*392
    __nv_bfloat16* Bc0 = (__nv_bfloat16*)(smraw + 63488);    // 96*104
    __nv_bfloat16* Bc1 = (__nv_bfloat16*)(smraw + 83456);    // 96*104
    const int tid = threadIdx.x, lane = tid & 31, wid = tid >> 5;
    const int rt = wid & 3, cw = wid >> 2;
    const uint32_t a_base = smem_u32(As), h_base = smem_u32(Hs);
    uint32_t bbase[2] = { smem_u32(Bc0), smem_u32(Bc1) };
    uint4* bdst[2] = { (uint4*)Bc0, (uint4*)Bc1 };

    {
        const __nv_bfloat16* a0 = g_x2 + (size_t)blockIdx.x * 64 * 96;
        for (int i = tid; i < 64 * 12; i += 384) {
            int r = i / 12, c8 = i % 12;
            *(uint4*)(As + r * 104 + c8 * 8) = *(const uint4*)(a0 + (size_t)r * 96 + c8 * 8);
        }
        const uint4* src = (const uint4*)g_w1;
        for (int i = tid; i < 1248; i += 384) bdst[0][i] = src[i];
    }
    __syncthreads();

    // ---------- fc1 + GELU -> Hs, pipelined weight staging ----------
    for (int ch = 0; ch < 4; ch++) {
        {
            const uint4* src = (ch < 3) ? (const uint4*)(g_w1 + (ch + 1) * 96 * 104)
                                        : (const uint4*)(g_w2[0]);
            uint4* d = bdst[(ch + 1) & 1];
            for (int i = tid; i < 1248; i += 384) d[i] = src[i];
        }
        float c[4][4];
        #pragma unroll
        for (int j = 0; j < 4; j++) { c[j][0]=0.f; c[j][1]=0.f; c[j][2]=0.f; c[j][3]=0.f; }
        wgemm_16x32<104, 104>(c, a_base, bbase[ch & 1], lane, rt * 16, cw * 32);
        int row0 = rt * 16 + (lane >> 2);
        #pragma unroll
        for (int j = 0; j < 4; j++) {
            int col = ch * 96 + cw * 32 + j * 8 + (lane & 3) * 2;
            float bi0 = __ldg(fc1_b + col), bi1 = __ldg(fc1_b + col + 1);
            float v0 = c[j][0] + bi0, v1 = c[j][1] + bi1;
            float v2 = c[j][2] + bi0, v3 = c[j][3] + bi1;
            v0 = 0.5f * v0 * (1.0f + erff(v0 * 0.70710678118654752f));
            v1 = 0.5f * v1 * (1.0f + erff(v1 * 0.70710678118654752f));
            v2 = 0.5f * v2 * (1.0f + erff(v2 * 0.70710678118654752f));
            v3 = 0.5f * v3 * (1.0f + erff(v3 * 0.70710678118654752f));
            *(uint32_t*)(Hs + row0 * 392 + col)       = packbf2(v0, v1);
            *(uint32_t*)(Hs + (row0 + 8) * 392 + col) = packbf2(v2, v3);
        }
        __syncthreads();
    }

    // ---------- fc2: accumulate over 4 K-chunks from Hs ----------
    float c2[4][4];
    #pragma unroll
    for (int j = 0; j < 4; j++) { c2[j][0]=0.f; c2[j][1]=0.f; c2[j][2]=0.f; c2[j][3]=0.f; }
    for (int kc = 0; kc < 4; kc++) {
        if (kc < 3) {
            const uint4* src = (const uint4*)(g_w2[kc + 1]);
            uint4* d = bdst[(kc + 1) & 1];
            for (int i = tid; i < 1248; i += 384) d[i] = src[i];
        }
        wgemm_16x32<392, 104>(c2, h_base + kc * 192, bbase[kc & 1], lane, rt * 16, cw * 32);
        __syncthreads();
    }

    // ---------- bias + residual -> out ----------
    const size_t row0 = (size_t)blockIdx.x * 64 + rt * 16 + (lane >> 2);
    #pragma unroll
    for (int j = 0; j < 4; j++) {
        int col = cw * 32 + j * 8 + (lane & 3) * 2;
        float bi0 = __ldg(fc2_b + col), bi1 = __ldg(fc2_b + col + 1);
        float2 r0 = *(const float2*)(g_x1 + row0 * 96 + col);
        float2 r1 = *(const float2*)(g_x1 + (row0 + 8) * 96 + col);
        *(float2*)(out + row0 * 96 + col)       = make_float2(c2[j][0] + bi0 + r0.x, c2[j][1] + bi1 + r0.y);
        *(float2*)(out + (row0 + 8) * 96 + col) = make_float2(c2[j][2] + bi0 + r1.x, c2[j][3] + bi1 + r1.y);
    }
}

// =====================================================================
extern "C" void kernel_launch(void* const* d_in, const int* in_sizes, int n_in,
                              void* d_out, int out_size)
{
    (void)in_sizes; (void)n_in; (void)out_size;
    const float* x      = (const float*)d_in[0];
    const float* n1g    = (const float*)d_in[2];
    const float* n1b    = (const float*)d_in[3];
    const float* qkv_w  = (const float*)d_in[4];
    const float* qkv_b  = (const float*)d_in[5];
    const float* proj_w = (const float*)d_in[6];
    const float* proj_b = (const float*)d_in[7];
    const float* n2g    = (const float*)d_in[8];
    const float* n2b    = (const float*)d_in[9];
    const float* fc1_w  = (const float*)d_in[10];
    const float* fc1_b  = (const float*)d_in[11];
    const float* fc2_w  = (const float*)d_in[12];
    const float* fc2_b  = (const float*)d_in[13];
    float* out = (float*)d_out;

    const int smAttn = 71296;
    const int smMlp  = 103424;

    cudaFuncSetAttribute(attn_kernel, cudaFuncAttributeMaxDynamicSharedMemorySize, smAttn);
    cudaFuncSetAttribute(mlp_kernel,  cudaFuncAttributeMaxDynamicSharedMemorySize, smMlp);

    prep_weights<<<432, 256>>>(qkv_w, proj_w, fc1_w, fc2_w);
    attn_kernel<<<8192, 384, smAttn>>>(x, n1g, n1b, qkv_b, proj_b, n2g, n2b);
    mlp_kernel<<<NTOKENS/64, 384, smMlp>>>(fc1_b, fc2_b, out);
}